// round 2
// baseline (speedup 1.0000x reference)
#include <cuda_runtime.h>

// ---------------------------------------------------------------------------
// ContractiveInvertibleGNN fused kernel (fp32 baseline)
//
// Math (group_mask == I):
//   h1[b,i,:]  = lrelu(X[b,i]*g_W1[i,:] + c_g[i,:])          c_g = E@g_W1[32:]+g_b1
//   h2         = h1 + lrelu(h1 @ g_W2 + g_b2)
//   e[b,i,:]   = h2 @ g_W3 + g_b3                            (128->32)
//   ag[b,i,:]  = sum_j Wadj[j,i] * e[b,j,:]                  (node mixing)
//   p1         = lrelu(ag @ f_W1[:32] + c_f[i,:])            c_f = E@f_W1[32:]+f_b1
//   p2         = p1 + lrelu(p1 @ f_W2 + f_b2)
//   out[b,i]   = dot(p2[b,i,:], f_W3[:,i]) + f_b3[i]
//
// One CTA = 4 batch elements = 128 (b,i)-rows. Everything stays in SMEM.
// ---------------------------------------------------------------------------

#define SMEM_FLOATS 42656
#define SMEM_BYTES  (SMEM_FLOATS * 4)

__device__ float d_cg[32 * 128];
__device__ float d_cf[32 * 128];
__device__ float d_wadjT[32 * 32];

__device__ __forceinline__ float lrelu(float x) { return x > 0.f ? x : 0.01f * x; }

// K-major activation buffer index with XOR chunk swizzle (float4-safe).
// element (k, m) -> sA[aidx(k,m)]
__device__ __forceinline__ int aidx(int k, int m) {
    return (k << 7) | (m ^ (((k >> 3) & 7) << 2));
}

// ---------------------------------------------------------------------------
__global__ void setup_kernel(const float* __restrict__ W, const float* __restrict__ emb,
                             const float* __restrict__ gW1, const float* __restrict__ gb1,
                             const float* __restrict__ fW1, const float* __restrict__ fb1) {
    int t = blockIdx.x * blockDim.x + threadIdx.x;
    if (t < 4096) {
        int i = t >> 7, a = t & 127;
        float sg = gb1[a], sf = fb1[a];
        #pragma unroll
        for (int e = 0; e < 32; ++e) {
            float em = emb[i * 32 + e];
            sg = fmaf(em, gW1[(32 + e) * 128 + a], sg);
            sf = fmaf(em, fW1[(32 + e) * 128 + a], sf);
        }
        d_cg[t] = sg;
        d_cf[t] = sf;
    }
    if (t < 1024) {
        int i = t >> 5, j = t & 31;
        d_wadjT[t] = (i == j) ? 0.f : W[j * 32 + i];  // Wadj[j,i], zero diag
    }
}

// 128xN GEMM micro-kernel: C[8][8] += A(K-major,swizzled) @ W(row-major,pitch 128)
__device__ __forceinline__ void gemm_nn(const float* __restrict__ sAp,
                                        const float* __restrict__ sWp,
                                        int K, int ty, int tx, float C[8][8]) {
    #pragma unroll
    for (int u = 0; u < 8; ++u)
        #pragma unroll
        for (int v = 0; v < 8; ++v) C[u][v] = 0.f;
    #pragma unroll 4
    for (int k = 0; k < K; ++k) {
        float4 a0 = *(const float4*)&sAp[aidx(k, ty * 8)];
        float4 a1 = *(const float4*)&sAp[aidx(k, ty * 8 + 4)];
        float4 b0 = *(const float4*)&sWp[k * 128 + tx * 8];
        float4 b1 = *(const float4*)&sWp[k * 128 + tx * 8 + 4];
        float av[8] = {a0.x, a0.y, a0.z, a0.w, a1.x, a1.y, a1.z, a1.w};
        float bv[8] = {b0.x, b0.y, b0.z, b0.w, b1.x, b1.y, b1.z, b1.w};
        #pragma unroll
        for (int u = 0; u < 8; ++u)
            #pragma unroll
            for (int v = 0; v < 8; ++v)
                C[u][v] = fmaf(av[u], bv[v], C[u][v]);
    }
}

__global__ __launch_bounds__(256, 1)
void fused_gnn_kernel(const float* __restrict__ X,
                      const float* __restrict__ gW1,
                      const float* __restrict__ gW2, const float* __restrict__ gb2,
                      const float* __restrict__ gW3, const float* __restrict__ gb3,
                      const float* __restrict__ fW1,
                      const float* __restrict__ fW2, const float* __restrict__ fb2,
                      const float* __restrict__ fW3, const float* __restrict__ fb3,
                      float* __restrict__ out) {
    extern __shared__ float sm[];
    float* sA   = sm;           // 16384 : activations, K-major swizzled
    float* sW   = sm + 16384;   // 16384 : current weight matrix
    float* sE   = sm + 32768;   // 128*36: e values, row-major pitch 36
    float* sAg  = sm + 37376;   // 4096  : aggregated, K-major swizzled (K=32)
    float* sAdj = sm + 41472;   // 32*33 : Wadj^T with pad
    float* sX   = sm + 42528;   // 128

    const int tid  = threadIdx.x;
    const int tx   = tid & 15, ty = tid >> 4;    // GEMM thread tile coords
    const int row2 = tid >> 1, half = tid & 1;   // 2 threads per row

    // ---- stage 0: load inputs / weights ----
    if (tid < 128) sX[tid] = X[blockIdx.x * 128 + tid];
    for (int idx = tid; idx < 1024; idx += 256)
        sAdj[(idx >> 5) * 33 + (idx & 31)] = d_wadjT[idx];
    {
        const float4* src = (const float4*)gW2;
        float4* dst = (float4*)sW;
        #pragma unroll
        for (int it = 0; it < 16; ++it) dst[it * 256 + tid] = src[it * 256 + tid];
    }
    __syncthreads();

    // ---- stage 1: produce h1 into sA ----
    {
        float xv = sX[row2];
        int i = row2 & 31;
        const float* w1r = gW1 + i * 128;
        const float* cgr = d_cg + i * 128;
        #pragma unroll 8
        for (int j = 0; j < 64; ++j) {
            int a = half * 64 + j;
            sA[aidx(a, row2)] = lrelu(fmaf(xv, w1r[a], cgr[a]));
        }
    }
    __syncthreads();

    float C[8][8];

    // ---- stage 2: h2 = h1 + lrelu(h1 @ gW2 + gb2) ----
    gemm_nn(sA, sW, 128, ty, tx, C);
    __syncthreads();
    {
        #pragma unroll
        for (int v = 0; v < 8; ++v) {
            int n = tx * 8 + v;
            float bias = gb2[n];
            float4 r0 = *(const float4*)&sA[aidx(n, ty * 8)];
            float4 r1 = *(const float4*)&sA[aidx(n, ty * 8 + 4)];
            float rv[8] = {r0.x, r0.y, r0.z, r0.w, r1.x, r1.y, r1.z, r1.w};
            #pragma unroll
            for (int u = 0; u < 8; ++u) C[u][v] = rv[u] + lrelu(C[u][v] + bias);
        }
        // overlap: stage gW3 (128x32) into sW
        const float4* src = (const float4*)gW3;
        float4* dst = (float4*)sW;
        #pragma unroll
        for (int it = 0; it < 4; ++it) dst[it * 256 + tid] = src[it * 256 + tid];
    }
    __syncthreads();
    #pragma unroll
    for (int v = 0; v < 8; ++v) {
        int n = tx * 8 + v;
        *(float4*)&sA[aidx(n, ty * 8)]     = make_float4(C[0][v], C[1][v], C[2][v], C[3][v]);
        *(float4*)&sA[aidx(n, ty * 8 + 4)] = make_float4(C[4][v], C[5][v], C[6][v], C[7][v]);
    }
    __syncthreads();

    // ---- stage 3: e = h2 @ gW3 + gb3  (N = 32) ----
    {
        float C2[8][2];
        #pragma unroll
        for (int u = 0; u < 8; ++u) { C2[u][0] = 0.f; C2[u][1] = 0.f; }
        #pragma unroll 4
        for (int k = 0; k < 128; ++k) {
            float4 a0 = *(const float4*)&sA[aidx(k, ty * 8)];
            float4 a1 = *(const float4*)&sA[aidx(k, ty * 8 + 4)];
            float2 b  = *(const float2*)&sW[k * 32 + tx * 2];
            float av[8] = {a0.x, a0.y, a0.z, a0.w, a1.x, a1.y, a1.z, a1.w};
            #pragma unroll
            for (int u = 0; u < 8; ++u) {
                C2[u][0] = fmaf(av[u], b.x, C2[u][0]);
                C2[u][1] = fmaf(av[u], b.y, C2[u][1]);
            }
        }
        float b3a = gb3[tx * 2], b3b = gb3[tx * 2 + 1];
        #pragma unroll
        for (int u = 0; u < 8; ++u) {
            int m = ty * 8 + u;
            sE[m * 36 + tx * 2]     = C2[u][0] + b3a;
            sE[m * 36 + tx * 2 + 1] = C2[u][1] + b3b;
        }
    }
    __syncthreads();

    // ---- stage 4: aggregation ag[b,i,:] = sum_j Wadj[j,i] e[b,j,:] ----
    {
        float acc[16];
        #pragma unroll
        for (int d = 0; d < 16; ++d) acc[d] = 0.f;
        int i = row2 & 31;
        int bbase = row2 & ~31;
        #pragma unroll 4
        for (int j = 0; j < 32; ++j) {
            float w = sAdj[i * 33 + j];
            const float* er = &sE[(bbase + j) * 36 + half * 16];
            #pragma unroll
            for (int q = 0; q < 4; ++q) {
                float4 ev = *(const float4*)&er[q * 4];
                acc[q * 4 + 0] = fmaf(w, ev.x, acc[q * 4 + 0]);
                acc[q * 4 + 1] = fmaf(w, ev.y, acc[q * 4 + 1]);
                acc[q * 4 + 2] = fmaf(w, ev.z, acc[q * 4 + 2]);
                acc[q * 4 + 3] = fmaf(w, ev.w, acc[q * 4 + 3]);
            }
        }
        #pragma unroll
        for (int d = 0; d < 16; ++d) sAg[aidx(half * 16 + d, row2)] = acc[d];
        // overlap: stage fW1[0:32,:] into sW
        const float4* src = (const float4*)fW1;
        float4* dst = (float4*)sW;
        #pragma unroll
        for (int it = 0; it < 4; ++it) dst[it * 256 + tid] = src[it * 256 + tid];
    }
    __syncthreads();

    // ---- stage 5: p1 = lrelu(ag @ fW1[:32] + c_f)  (K = 32) ----
    gemm_nn(sAg, sW, 32, ty, tx, C);
    __syncthreads();
    {
        #pragma unroll
        for (int u = 0; u < 8; ++u) {
            int m = ty * 8 + u;
            const float* cfr = d_cf + (m & 31) * 128;
            #pragma unroll
            for (int v = 0; v < 8; ++v) {
                int n = tx * 8 + v;
                C[u][v] = lrelu(C[u][v] + cfr[n]);
            }
        }
        #pragma unroll
        for (int v = 0; v < 8; ++v) {
            int n = tx * 8 + v;
            *(float4*)&sA[aidx(n, ty * 8)]     = make_float4(C[0][v], C[1][v], C[2][v], C[3][v]);
            *(float4*)&sA[aidx(n, ty * 8 + 4)] = make_float4(C[4][v], C[5][v], C[6][v], C[7][v]);
        }
        // overlap: stage fW2 into sW
        const float4* src = (const float4*)fW2;
        float4* dst = (float4*)sW;
        #pragma unroll
        for (int it = 0; it < 16; ++it) dst[it * 256 + tid] = src[it * 256 + tid];
    }
    __syncthreads();

    // ---- stage 6: p2 = p1 + lrelu(p1 @ fW2 + fb2) ----
    gemm_nn(sA, sW, 128, ty, tx, C);
    __syncthreads();
    {
        #pragma unroll
        for (int v = 0; v < 8; ++v) {
            int n = tx * 8 + v;
            float bias = fb2[n];
            float4 r0 = *(const float4*)&sA[aidx(n, ty * 8)];
            float4 r1 = *(const float4*)&sA[aidx(n, ty * 8 + 4)];
            float rv[8] = {r0.x, r0.y, r0.z, r0.w, r1.x, r1.y, r1.z, r1.w};
            #pragma unroll
            for (int u = 0; u < 8; ++u) C[u][v] = rv[u] + lrelu(C[u][v] + bias);
        }
        // overlap: stage fW3 (128x32, [a][i]) into sW
        const float4* src = (const float4*)fW3;
        float4* dst = (float4*)sW;
        #pragma unroll
        for (int it = 0; it < 4; ++it) dst[it * 256 + tid] = src[it * 256 + tid];
    }
    __syncthreads();
    #pragma unroll
    for (int v = 0; v < 8; ++v) {
        int n = tx * 8 + v;
        *(float4*)&sA[aidx(n, ty * 8)]     = make_float4(C[0][v], C[1][v], C[2][v], C[3][v]);
        *(float4*)&sA[aidx(n, ty * 8 + 4)] = make_float4(C[4][v], C[5][v], C[6][v], C[7][v]);
    }
    __syncthreads();

    // ---- stage 7: out[b,i] = dot(p2[row,:], fW3[:,i]) + fb3[i] ----
    {
        int i = row2 & 31;
        float acc = 0.f;
        #pragma unroll 8
        for (int j = 0; j < 64; ++j) {
            int a = half * 64 + j;
            acc = fmaf(sA[aidx(a, row2)], sW[a * 32 + i], acc);
        }
        acc += __shfl_xor_sync(0xffffffffu, acc, 1);
        if (half == 0) out[blockIdx.x * 128 + row2] = acc + fb3[i];
    }
}

// ---------------------------------------------------------------------------
extern "C" void kernel_launch(void* const* d_in, const int* in_sizes, int n_in,
                              void* d_out, int out_size) {
    const float* X   = (const float*)d_in[0];
    const float* W   = (const float*)d_in[1];
    const float* emb = (const float*)d_in[2];
    const float* gW1 = (const float*)d_in[3];
    const float* gb1 = (const float*)d_in[4];
    const float* gW2 = (const float*)d_in[5];
    const float* gb2 = (const float*)d_in[6];
    const float* gW3 = (const float*)d_in[7];
    const float* gb3 = (const float*)d_in[8];
    const float* fW1 = (const float*)d_in[9];
    const float* fb1 = (const float*)d_in[10];
    const float* fW2 = (const float*)d_in[11];
    const float* fb2 = (const float*)d_in[12];
    const float* fW3 = (const float*)d_in[13];
    const float* fb3 = (const float*)d_in[14];
    float* out = (float*)d_out;

    int B = in_sizes[0] / 32;

    cudaFuncSetAttribute(fused_gnn_kernel,
                         cudaFuncAttributeMaxDynamicSharedMemorySize, SMEM_BYTES);

    setup_kernel<<<16, 256>>>(W, emb, gW1, gb1, fW1, fb1);
    fused_gnn_kernel<<<B / 4, 256, SMEM_BYTES>>>(X, gW1, gW2, gb2, gW3, gb3,
                                                 fW1, fW2, fb2, fW3, fb3, out);
}

// round 4
// speedup vs baseline: 1.1758x; 1.1758x over previous
#include <cuda_runtime.h>
#include <cuda_bf16.h>
#include <cstdint>

// ---------------------------------------------------------------------------
// ContractiveInvertibleGNN fused kernel — mma.sync (HMMA) bf16-split version.
//
// Math (group_mask == I):
//   h1[b,i,:]  = lrelu(X[b,i]*g_W1[i,:] + c_g[i,:])
//   h2         = h1 + lrelu(h1 @ g_W2 + g_b2)          <- MMA (M128 N128 K128)
//   e          = h2 @ g_W3 + g_b3                      <- MMA (N32)
//   ag[b,i,:]  = sum_j Wadj[j,i] * e[b,j,:]            <- FFMA
//   p1         = lrelu(ag @ f_W1[:32] + c_f[i,:])      <- MMA (K32)
//   p2         = p1 + lrelu(p1 @ f_W2 + f_b2)          <- MMA (M128 N128 K128)
//   out[b,i]   = dot(p2[b,i,:], f_W3[:,i]) + f_b3[i]   <- epilogue + shfl
//
// bf16 split: A=Ahi+Alo, B=Bhi+Blo; 3 passes AhiBhi + AloBhi + AhiBlo in fp32
// accumulators (dropped lo*lo <= 2^-16 per term). One CTA = 4 batch rows =
// 128 (b,i)-rows. Warp w owns M rows [16w, 16w+16), full N in registers.
// ---------------------------------------------------------------------------

// ---- SMEM layout (bytes) ----
#define PA 272          // activation row pitch (136 bf16)
#define PG 80           // K=32 row pitch (40 bf16)
#define OFF_AHI   0        // 34816
#define OFF_ALO   34816    // 34816
#define OFF_WHI   69632    // 34816 (stage weights hi / fW3 fp32 at end)
#define OFF_WLO   104448   // 34816
#define OFF_E     139264   // 18432 e fp32, pitch 36 floats
#define OFF_ADJ   157696   // 4224  WadjT pitch 33
#define OFF_X     161920   // 512
#define SMEM_BYTES 162432

// ---- preformatted weights (written by setup_kernel) ----
__device__ char  d_wg2h[34816], d_wg2l[34816];   // gW2^T [n=128][k=128] p272
__device__ char  d_wg3h[8704],  d_wg3l[8704];    // gW3^T [n=32 ][k=128] p272
__device__ char  d_wf1h[10240], d_wf1l[10240];   // fW1[:32]^T [n=128][k=32] p80
__device__ char  d_wf2h[34816], d_wf2l[34816];   // fW2^T [n=128][k=128] p272
__device__ float d_cg[4096], d_cf[4096], d_wadjT[1024];

__device__ __forceinline__ float lrelu(float x) { return x > 0.f ? x : 0.01f * x; }

__device__ __forceinline__ void splitw(float w, __nv_bfloat16& hi, __nv_bfloat16& lo) {
    hi = __float2bfloat16(w);
    lo = __float2bfloat16(w - __bfloat162float(hi));
}

__device__ __forceinline__ uint32_t smem_u32(const void* p) {
    uint32_t a;
    asm("{ .reg .u64 t; cvta.to.shared.u64 t, %1; cvt.u32.u64 %0, t; }" : "=r"(a) : "l"(p));
    return a;
}

#define LDSM_X4(r0, r1, r2, r3, addr)                                        \
    asm volatile("ldmatrix.sync.aligned.m8n8.x4.shared.b16 {%0,%1,%2,%3}, [%4];" \
                 : "=r"(r0), "=r"(r1), "=r"(r2), "=r"(r3) : "r"(addr))

__device__ __forceinline__ void mma16816(float* c, uint32_t a0, uint32_t a1,
                                         uint32_t a2, uint32_t a3,
                                         uint32_t b0, uint32_t b1) {
    asm volatile("mma.sync.aligned.m16n8k16.row.col.f32.bf16.bf16.f32 "
                 "{%0,%1,%2,%3}, {%4,%5,%6,%7}, {%8,%9}, {%0,%1,%2,%3};"
                 : "+f"(c[0]), "+f"(c[1]), "+f"(c[2]), "+f"(c[3])
                 : "r"(a0), "r"(a1), "r"(a2), "r"(a3), "r"(b0), "r"(b1));
}

// 3-pass split GEMM. A rows [m0, m0+16), all NT n8-tiles, KS k16-steps.
// aP/wP = row pitches in bytes. C[nt][4] fp32 fragments (NOT zeroed here).
template <int KS, int NT>
__device__ __forceinline__ void gemm3(uint32_t aHi, uint32_t aLo,
                                      uint32_t wHi, uint32_t wLo,
                                      int aP, int wP, int lane, int m0,
                                      float C[][4]) {
    const uint32_t aOff = (uint32_t)((m0 + (lane & 15)) * aP + (lane >> 4) * 16);
    const uint32_t wOff = (uint32_t)(((lane & 7) + 8 * ((lane >> 3) & 1)) * wP
                                     + (lane >> 4) * 16);
    #pragma unroll
    for (int pass = 0; pass < 3; ++pass) {
        const uint32_t aB = (pass == 1 ? aLo : aHi) + aOff;
        const uint32_t wB = (pass == 2 ? wLo : wHi) + wOff;
        #pragma unroll
        for (int k = 0; k < KS; ++k) {
            uint32_t a0, a1, a2, a3;
            LDSM_X4(a0, a1, a2, a3, aB + k * 32);
            #pragma unroll
            for (int p = 0; p < NT / 2; ++p) {
                uint32_t b0, b1, b2, b3;
                LDSM_X4(b0, b1, b2, b3, wB + p * 16 * wP + k * 32);
                mma16816(C[2 * p],     a0, a1, a2, a3, b0, b2);
                mma16816(C[2 * p + 1], a0, a1, a2, a3, b1, b3);
            }
        }
    }
}

// ---------------------------------------------------------------------------
__global__ void setup_kernel(const float* __restrict__ W, const float* __restrict__ emb,
                             const float* __restrict__ gW1, const float* __restrict__ gb1,
                             const float* __restrict__ gW2, const float* __restrict__ gW3,
                             const float* __restrict__ fW1, const float* __restrict__ fb1,
                             const float* __restrict__ fW2) {
    int t = blockIdx.x * blockDim.x + threadIdx.x;
    if (t < 4096) {
        int i = t >> 7, a = t & 127;
        float sg = gb1[a], sf = fb1[a];
        #pragma unroll
        for (int e = 0; e < 32; ++e) {
            float em = emb[i * 32 + e];
            sg = fmaf(em, gW1[(32 + e) * 128 + a], sg);
            sf = fmaf(em, fW1[(32 + e) * 128 + a], sf);
        }
        d_cg[t] = sg;
        d_cf[t] = sf;
    }
    if (t < 1024) {
        int i = t >> 5, j = t & 31;
        d_wadjT[t] = (i == j) ? 0.f : W[j * 32 + i];
    }
    __nv_bfloat16 hi, lo;
    if (t < 16384) {                       // gW2^T: n=t>>7, k=t&127
        int n = t >> 7, k = t & 127;
        splitw(gW2[k * 128 + n], hi, lo);
        uint32_t o = n * PA + k * 2;
        *(__nv_bfloat16*)(d_wg2h + o) = hi;
        *(__nv_bfloat16*)(d_wg2l + o) = lo;
    } else if (t < 20480) {                // gW3^T: n 0..31, k 0..127
        int u = t - 16384, n = u >> 7, k = u & 127;
        splitw(gW3[k * 32 + n], hi, lo);
        uint32_t o = n * PA + k * 2;
        *(__nv_bfloat16*)(d_wg3h + o) = hi;
        *(__nv_bfloat16*)(d_wg3l + o) = lo;
    } else if (t < 24576) {                // fW1[:32]^T: n 0..127, k 0..31
        int u = t - 20480, n = u >> 5, k = u & 31;
        splitw(fW1[k * 128 + n], hi, lo);
        uint32_t o = n * PG + k * 2;
        *(__nv_bfloat16*)(d_wf1h + o) = hi;
        *(__nv_bfloat16*)(d_wf1l + o) = lo;
    } else if (t < 40960) {                // fW2^T
        int u = t - 24576, n = u >> 7, k = u & 127;
        splitw(fW2[k * 128 + n], hi, lo);
        uint32_t o = n * PA + k * 2;
        *(__nv_bfloat16*)(d_wf2h + o) = hi;
        *(__nv_bfloat16*)(d_wf2l + o) = lo;
    }
}

// copy `size` bytes (multiple of 16) global->shared with 256 threads
__device__ __forceinline__ void blockcopy(char* dst, const char* src, int size, int tid) {
    for (int o = tid * 16; o < size; o += 4096)
        *(float4*)(dst + o) = *(const float4*)(src + o);
}

// ---------------------------------------------------------------------------
__global__ __launch_bounds__(256, 1)
void fused_gnn_kernel(const float* __restrict__ X,
                      const float* __restrict__ gW1,
                      const float* __restrict__ gb2, const float* __restrict__ gb3,
                      const float* __restrict__ fb2,
                      const float* __restrict__ fW3, const float* __restrict__ fb3,
                      float* __restrict__ out) {
    extern __shared__ char sm[];
    const uint32_t smb = smem_u32(sm);
    const int tid = threadIdx.x;
    const int wid = tid >> 5, lane = tid & 31;
    const int m0 = wid * 16;
    const int row2 = tid >> 1, half = tid & 1;   // gen/agg mapping: 2 thr/row

    char*  sAh = sm + OFF_AHI;
    char*  sAl = sm + OFF_ALO;
    char*  sWh = sm + OFF_WHI;
    char*  sWl = sm + OFF_WLO;
    float* sE   = (float*)(sm + OFF_E);
    float* sAdj = (float*)(sm + OFF_ADJ);
    float* sX   = (float*)(sm + OFF_X);
    const uint32_t uAh = smb + OFF_AHI, uAl = smb + OFF_ALO;
    const uint32_t uWh = smb + OFF_WHI, uWl = smb + OFF_WLO;

    // fragment->element mapping for epilogues
    const int r0 = m0 + (lane >> 2), r1 = r0 + 8;
    const int c2 = 2 * (lane & 3);

    // ---- stage 0: inputs + gW2 staging ----
    if (tid < 128) sX[tid] = X[blockIdx.x * 128 + tid];
    for (int idx = tid; idx < 1024; idx += 256)
        sAdj[(idx >> 5) * 33 + (idx & 31)] = d_wadjT[idx];
    blockcopy(sWh, d_wg2h, 34816, tid);
    blockcopy(sWl, d_wg2l, 34816, tid);

    // ---- stage 1: h1 -> split bf16 into sA (pitch PA) ----
    {
        float xv = X[blockIdx.x * 128 + row2];
        int i = row2 & 31;
        const float* w1r = gW1 + i * 128;
        const float* cgr = d_cg + i * 128;
        #pragma unroll 8
        for (int kk = 0; kk < 64; kk += 2) {
            int k = half * 64 + kk;
            float h0 = lrelu(fmaf(xv, __ldg(w1r + k),     __ldg(cgr + k)));
            float h1v= lrelu(fmaf(xv, __ldg(w1r + k + 1), __ldg(cgr + k + 1)));
            __nv_bfloat162 vh, vl;
            splitw(h0,  vh.x, vl.x);
            splitw(h1v, vh.y, vl.y);
            *(__nv_bfloat162*)(sAh + row2 * PA + k * 2) = vh;
            *(__nv_bfloat162*)(sAl + row2 * PA + k * 2) = vl;
        }
    }
    __syncthreads();

    float C[16][4];

    // ---- stage 2: h1 @ gW2 (K128, N128) ----
    #pragma unroll
    for (int n = 0; n < 16; ++n) { C[n][0] = C[n][1] = C[n][2] = C[n][3] = 0.f; }
    gemm3<8, 16>(uAh, uAl, uWh, uWl, PA, PA, lane, m0, C);
    // epilogue: h2 = h1 + lrelu(C + gb2)  (warp-private rows, in-place)
    #pragma unroll
    for (int nt = 0; nt < 16; ++nt) {
        int col = nt * 8 + c2;
        float b0 = __ldg(gb2 + col), b1 = __ldg(gb2 + col + 1);
        {
            __nv_bfloat162 hh = *(__nv_bfloat162*)(sAh + r0 * PA + col * 2);
            __nv_bfloat162 ll = *(__nv_bfloat162*)(sAl + r0 * PA + col * 2);
            float v0 = __bfloat162float(hh.x) + __bfloat162float(ll.x) + lrelu(C[nt][0] + b0);
            float v1 = __bfloat162float(hh.y) + __bfloat162float(ll.y) + lrelu(C[nt][1] + b1);
            __nv_bfloat162 vh, vl; splitw(v0, vh.x, vl.x); splitw(v1, vh.y, vl.y);
            *(__nv_bfloat162*)(sAh + r0 * PA + col * 2) = vh;
            *(__nv_bfloat162*)(sAl + r0 * PA + col * 2) = vl;
        }
        {
            __nv_bfloat162 hh = *(__nv_bfloat162*)(sAh + r1 * PA + col * 2);
            __nv_bfloat162 ll = *(__nv_bfloat162*)(sAl + r1 * PA + col * 2);
            float v0 = __bfloat162float(hh.x) + __bfloat162float(ll.x) + lrelu(C[nt][2] + b0);
            float v1 = __bfloat162float(hh.y) + __bfloat162float(ll.y) + lrelu(C[nt][3] + b1);
            __nv_bfloat162 vh, vl; splitw(v0, vh.x, vl.x); splitw(v1, vh.y, vl.y);
            *(__nv_bfloat162*)(sAh + r1 * PA + col * 2) = vh;
            *(__nv_bfloat162*)(sAl + r1 * PA + col * 2) = vl;
        }
    }
    __syncthreads();                 // all warps done with gW2 + h2 complete
    blockcopy(sWh, d_wg3h, 8704, tid);
    blockcopy(sWl, d_wg3l, 8704, tid);
    __syncthreads();

    // ---- stage 3: e = h2 @ gW3 (K128, N32) ----
    #pragma unroll
    for (int n = 0; n < 4; ++n) { C[n][0] = C[n][1] = C[n][2] = C[n][3] = 0.f; }
    gemm3<8, 4>(uAh, uAl, uWh, uWl, PA, PA, lane, m0, C);
    #pragma unroll
    for (int nt = 0; nt < 4; ++nt) {
        int col = nt * 8 + c2;
        float b0 = __ldg(gb3 + col), b1 = __ldg(gb3 + col + 1);
        *(float2*)&sE[r0 * 36 + col] = make_float2(C[nt][0] + b0, C[nt][1] + b1);
        *(float2*)&sE[r1 * 36 + col] = make_float2(C[nt][2] + b0, C[nt][3] + b1);
    }
    __syncthreads();                 // e complete; all warps done with gW3 + h2(A)
    blockcopy(sWh, d_wf1h, 10240, tid);
    blockcopy(sWl, d_wf1l, 10240, tid);

    // ---- stage 4: aggregation -> split bf16 ag (pitch PG, K=32) ----
    {
        float acc[16];
        #pragma unroll
        for (int d = 0; d < 16; ++d) acc[d] = 0.f;
        int i = row2 & 31;
        int bbase = row2 & ~31;
        #pragma unroll 4
        for (int j = 0; j < 32; ++j) {
            float w = sAdj[i * 33 + j];
            const float* er = &sE[(bbase + j) * 36 + half * 16];
            #pragma unroll
            for (int q = 0; q < 4; ++q) {
                float4 ev = *(const float4*)&er[q * 4];
                acc[q * 4 + 0] = fmaf(w, ev.x, acc[q * 4 + 0]);
                acc[q * 4 + 1] = fmaf(w, ev.y, acc[q * 4 + 1]);
                acc[q * 4 + 2] = fmaf(w, ev.z, acc[q * 4 + 2]);
                acc[q * 4 + 3] = fmaf(w, ev.w, acc[q * 4 + 3]);
            }
        }
        #pragma unroll
        for (int d = 0; d < 16; d += 2) {
            int k = half * 16 + d;
            __nv_bfloat162 vh, vl;
            splitw(acc[d],     vh.x, vl.x);
            splitw(acc[d + 1], vh.y, vl.y);
            *(__nv_bfloat162*)(sAh + row2 * PG + k * 2) = vh;
            *(__nv_bfloat162*)(sAl + row2 * PG + k * 2) = vl;
        }
    }
    __syncthreads();

    // ---- stage 5: p1 = lrelu(ag @ fW1 + c_f)  (K32, N128) ----
    #pragma unroll
    for (int n = 0; n < 16; ++n) { C[n][0] = C[n][1] = C[n][2] = C[n][3] = 0.f; }
    gemm3<2, 16>(uAh, uAl, uWh, uWl, PG, PG, lane, m0, C);
    __syncthreads();                 // all warps done reading ag + fW1
    blockcopy(sWh, d_wf2h, 34816, tid);
    blockcopy(sWl, d_wf2l, 34816, tid);
    {
        const float* cf0 = d_cf + (r0 & 31) * 128;
        const float* cf1 = d_cf + (r1 & 31) * 128;
        #pragma unroll
        for (int nt = 0; nt < 16; ++nt) {
            int col = nt * 8 + c2;
            float v0 = lrelu(C[nt][0] + __ldg(cf0 + col));
            float v1 = lrelu(C[nt][1] + __ldg(cf0 + col + 1));
            float v2 = lrelu(C[nt][2] + __ldg(cf1 + col));
            float v3 = lrelu(C[nt][3] + __ldg(cf1 + col + 1));
            __nv_bfloat162 vh, vl;
            splitw(v0, vh.x, vl.x); splitw(v1, vh.y, vl.y);
            *(__nv_bfloat162*)(sAh + r0 * PA + col * 2) = vh;
            *(__nv_bfloat162*)(sAl + r0 * PA + col * 2) = vl;
            splitw(v2, vh.x, vl.x); splitw(v3, vh.y, vl.y);
            *(__nv_bfloat162*)(sAh + r1 * PA + col * 2) = vh;
            *(__nv_bfloat162*)(sAl + r1 * PA + col * 2) = vl;
        }
    }
    __syncthreads();

    // ---- stage 6: p1 @ fW2 (K128, N128) ----
    #pragma unroll
    for (int n = 0; n < 16; ++n) { C[n][0] = C[n][1] = C[n][2] = C[n][3] = 0.f; }
    gemm3<8, 16>(uAh, uAl, uWh, uWl, PA, PA, lane, m0, C);
    __syncthreads();                 // all warps done with fW2
    blockcopy(sWh, (const char*)fW3, 16384, tid);   // fW3 fp32 [a=128][i=32]
    __syncthreads();

    // ---- stage 7: p2 + output dot ----
    {
        const float* sW3 = (const float*)sWh;
        const int i0 = r0 & 31, i1 = r1 & 31;
        float acc0 = 0.f, acc1 = 0.f;
        #pragma unroll
        for (int nt = 0; nt < 16; ++nt) {
            int col = nt * 8 + c2;
            float b0 = __ldg(fb2 + col), b1 = __ldg(fb2 + col + 1);
            {
                __nv_bfloat162 hh = *(__nv_bfloat162*)(sAh + r0 * PA + col * 2);
                __nv_bfloat162 ll = *(__nv_bfloat162*)(sAl + r0 * PA + col * 2);
                float p2a = __bfloat162float(hh.x) + __bfloat162float(ll.x) + lrelu(C[nt][0] + b0);
                float p2b = __bfloat162float(hh.y) + __bfloat162float(ll.y) + lrelu(C[nt][1] + b1);
                acc0 = fmaf(p2a, sW3[col * 32 + i0], acc0);
                acc0 = fmaf(p2b, sW3[(col + 1) * 32 + i0], acc0);
            }
            {
                __nv_bfloat162 hh = *(__nv_bfloat162*)(sAh + r1 * PA + col * 2);
                __nv_bfloat162 ll = *(__nv_bfloat162*)(sAl + r1 * PA + col * 2);
                float p2a = __bfloat162float(hh.x) + __bfloat162float(ll.x) + lrelu(C[nt][2] + b0);
                float p2b = __bfloat162float(hh.y) + __bfloat162float(ll.y) + lrelu(C[nt][3] + b1);
                acc1 = fmaf(p2a, sW3[col * 32 + i1], acc1);
                acc1 = fmaf(p2b, sW3[(col + 1) * 32 + i1], acc1);
            }
        }
        acc0 += __shfl_xor_sync(0xffffffffu, acc0, 1);
        acc0 += __shfl_xor_sync(0xffffffffu, acc0, 2);
        acc1 += __shfl_xor_sync(0xffffffffu, acc1, 1);
        acc1 += __shfl_xor_sync(0xffffffffu, acc1, 2);
        if ((lane & 3) == 0) {
            out[blockIdx.x * 128 + r0] = acc0 + __ldg(fb3 + i0);
            out[blockIdx.x * 128 + r1] = acc1 + __ldg(fb3 + i1);
        }
    }
}

// ---------------------------------------------------------------------------
extern "C" void kernel_launch(void* const* d_in, const int* in_sizes, int n_in,
                              void* d_out, int out_size) {
    const float* X   = (const float*)d_in[0];
    const float* W   = (const float*)d_in[1];
    const float* emb = (const float*)d_in[2];
    const float* gW1 = (const float*)d_in[3];
    const float* gb1 = (const float*)d_in[4];
    const float* gW2 = (const float*)d_in[5];
    const float* gb2 = (const float*)d_in[6];
    const float* gW3 = (const float*)d_in[7];
    const float* gb3 = (const float*)d_in[8];
    const float* fW1 = (const float*)d_in[9];
    const float* fb1 = (const float*)d_in[10];
    const float* fW2 = (const float*)d_in[11];
    const float* fb2 = (const float*)d_in[12];
    const float* fW3 = (const float*)d_in[13];
    const float* fb3 = (const float*)d_in[14];
    float* out = (float*)d_out;

    int B = in_sizes[0] / 32;

    cudaFuncSetAttribute(fused_gnn_kernel,
                         cudaFuncAttributeMaxDynamicSharedMemorySize, SMEM_BYTES);

    setup_kernel<<<160, 256>>>(W, emb, gW1, gb1, gW2, gW3, fW1, fb1, fW2);
    fused_gnn_kernel<<<B / 4, 256, SMEM_BYTES>>>(X, gW1, gb2, gb3, fb2, fW3, fb3, out);
}

// round 5
// speedup vs baseline: 1.4515x; 1.2345x over previous
#include <cuda_runtime.h>
#include <cuda_bf16.h>
#include <cstdint>

// ---------------------------------------------------------------------------
// ContractiveInvertibleGNN fused kernel — mma.sync bf16-split, 16-warp version.
//
//   h1[b,i,:]  = lrelu(X[b,i]*g_W1[i,:] + c_g[i,:])
//   h2         = h1 + lrelu(h1 @ g_W2 + g_b2)          <- MMA K128 N128
//   e          = h2 @ g_W3 + g_b3                      <- MMA K128 N32
//   ag[b,i,:]  = sum_j Wadj[j,i] * e[b,j,:]            <- FFMA
//   p1         = lrelu(ag @ f_W1[:32] + c_f[i,:])      <- MMA K32  N128
//   p2         = p1 + lrelu(p1 @ f_W2 + f_b2)          <- MMA K128 N128
//   out[b,i]   = dot(p2[b,i,:], f_W3[:,i]) + f_b3[i]
//
// bf16 split fused sweep: per k-step load Ahi/Alo once, per n-pair load
// Bhi/Blo once, accumulate AhiBhi + AloBhi + AhiBlo into one fp32 C.
// 512 threads: warp (mw = wid&7, nh = wid>>3) owns rows [16mw,16mw+16),
// cols [64nh, 64nh+64). Weights prefetched via cp.async into resident SMEM.
// ---------------------------------------------------------------------------

#define PA 272          // activation row pitch bytes (128 bf16 + pad)
#define PG 80           // K=32 row pitch bytes
// ---- SMEM layout (bytes, all 16-aligned) ----
#define OFF_AHI   0         // 34816
#define OFF_ALO   34816     // 34816
#define OFF_W     69632     // 69632  gW2 hi+lo, later fW2 hi+lo
#define OFF_G3    139264    // 17408  gW3 hi+lo (resident)
#define OFF_F1    156672    // 20480  fW1 hi+lo (resident)
#define OFF_F3    177152    // 16384  fW3 fp32 (resident)
#define OFF_E     193536    // 18432  e fp32, pitch 36 floats
#define OFF_ADJ   211968    // 4224   WadjT pitch 33
#define OFF_PART  216192    // 1024
#define SMEM_BYTES 217216

// ---- preformatted weights (written by setup_kernel) ----
__device__ __align__(256) char d_wg2h[34816], d_wg2l[34816]; // gW2^T [n128][k128] p272
__device__ __align__(256) char d_wg3h[8704],  d_wg3l[8704];  // gW3^T [n32][k128]  p272
__device__ __align__(256) char d_wf1h[10240], d_wf1l[10240]; // fW1^T [n128][k32]  p80
__device__ __align__(256) char d_wf2h[34816], d_wf2l[34816]; // fW2^T [n128][k128] p272
__device__ float d_cg[4096], d_cf[4096], d_wadjT[1024];

__device__ __forceinline__ float lrelu(float x) { return x > 0.f ? x : 0.01f * x; }

__device__ __forceinline__ void splitw(float w, __nv_bfloat16& hi, __nv_bfloat16& lo) {
    hi = __float2bfloat16(w);
    lo = __float2bfloat16(w - __bfloat162float(hi));
}

__device__ __forceinline__ uint32_t smem_u32(const void* p) {
    uint32_t a;
    asm("{ .reg .u64 t; cvta.to.shared.u64 t, %1; cvt.u32.u64 %0, t; }" : "=r"(a) : "l"(p));
    return a;
}

#define LDSM_X4(r0, r1, r2, r3, addr)                                        \
    asm volatile("ldmatrix.sync.aligned.m8n8.x4.shared.b16 {%0,%1,%2,%3}, [%4];" \
                 : "=r"(r0), "=r"(r1), "=r"(r2), "=r"(r3) : "r"(addr))

#define CP16(d, s) \
    asm volatile("cp.async.ca.shared.global [%0], [%1], 16;" \
                 :: "r"(d), "l"((unsigned long long)__cvta_generic_to_global(s)) : "memory")
#define CP_COMMIT() asm volatile("cp.async.commit_group;" ::: "memory")
#define CP_WAIT(n)  asm volatile("cp.async.wait_group %0;" :: "n"(n) : "memory")

__device__ __forceinline__ void mma16816(float* c, uint32_t a0, uint32_t a1,
                                         uint32_t a2, uint32_t a3,
                                         uint32_t b0, uint32_t b1) {
    asm volatile("mma.sync.aligned.m16n8k16.row.col.f32.bf16.bf16.f32 "
                 "{%0,%1,%2,%3}, {%4,%5,%6,%7}, {%8,%9}, {%0,%1,%2,%3};"
                 : "+f"(c[0]), "+f"(c[1]), "+f"(c[2]), "+f"(c[3])
                 : "r"(a0), "r"(a1), "r"(a2), "r"(a3), "r"(b0), "r"(b1));
}

// Fused 3-term split GEMM sweep. Addresses are pre-offset per thread.
template <int KS, int NPAIR, int WP>
__device__ __forceinline__ void gemm_fused(uint32_t aHiB, uint32_t aLoB,
                                           uint32_t wHiB, uint32_t wLoB,
                                           float C[][4]) {
    #pragma unroll
    for (int k = 0; k < KS; ++k) {
        uint32_t ah0, ah1, ah2, ah3, al0, al1, al2, al3;
        LDSM_X4(ah0, ah1, ah2, ah3, aHiB + k * 32);
        LDSM_X4(al0, al1, al2, al3, aLoB + k * 32);
        #pragma unroll
        for (int p = 0; p < NPAIR; ++p) {
            uint32_t bh0, bh1, bh2, bh3, bl0, bl1, bl2, bl3;
            LDSM_X4(bh0, bh1, bh2, bh3, wHiB + p * 16 * WP + k * 32);
            LDSM_X4(bl0, bl1, bl2, bl3, wLoB + p * 16 * WP + k * 32);
            mma16816(C[2 * p],     ah0, ah1, ah2, ah3, bh0, bh2);
            mma16816(C[2 * p + 1], ah0, ah1, ah2, ah3, bh1, bh3);
            mma16816(C[2 * p],     al0, al1, al2, al3, bh0, bh2);
            mma16816(C[2 * p + 1], al0, al1, al2, al3, bh1, bh3);
            mma16816(C[2 * p],     ah0, ah1, ah2, ah3, bl0, bl2);
            mma16816(C[2 * p + 1], ah0, ah1, ah2, ah3, bl1, bl3);
        }
    }
}

// ---------------------------------------------------------------------------
__global__ void setup_kernel(const float* __restrict__ W, const float* __restrict__ emb,
                             const float* __restrict__ gW1, const float* __restrict__ gb1,
                             const float* __restrict__ gW2, const float* __restrict__ gW3,
                             const float* __restrict__ fW1, const float* __restrict__ fb1,
                             const float* __restrict__ fW2) {
    int t = blockIdx.x * blockDim.x + threadIdx.x;
    if (t < 4096) {
        int i = t >> 7, a = t & 127;
        float sg = gb1[a], sf = fb1[a];
        #pragma unroll
        for (int e = 0; e < 32; ++e) {
            float em = emb[i * 32 + e];
            sg = fmaf(em, gW1[(32 + e) * 128 + a], sg);
            sf = fmaf(em, fW1[(32 + e) * 128 + a], sf);
        }
        d_cg[t] = sg;
        d_cf[t] = sf;
    }
    if (t < 1024) {
        int i = t >> 5, j = t & 31;
        d_wadjT[t] = (i == j) ? 0.f : W[j * 32 + i];
    }
    __nv_bfloat16 hi, lo;
    if (t < 16384) {                       // gW2^T
        int n = t >> 7, k = t & 127;
        splitw(gW2[k * 128 + n], hi, lo);
        uint32_t o = n * PA + k * 2;
        *(__nv_bfloat16*)(d_wg2h + o) = hi;
        *(__nv_bfloat16*)(d_wg2l + o) = lo;
    } else if (t < 20480) {                // gW3^T
        int u = t - 16384, n = u >> 7, k = u & 127;
        splitw(gW3[k * 32 + n], hi, lo);
        uint32_t o = n * PA + k * 2;
        *(__nv_bfloat16*)(d_wg3h + o) = hi;
        *(__nv_bfloat16*)(d_wg3l + o) = lo;
    } else if (t < 24576) {                // fW1[:32]^T
        int u = t - 20480, n = u >> 5, k = u & 31;
        splitw(fW1[k * 128 + n], hi, lo);
        uint32_t o = n * PG + k * 2;
        *(__nv_bfloat16*)(d_wf1h + o) = hi;
        *(__nv_bfloat16*)(d_wf1l + o) = lo;
    } else if (t < 40960) {                // fW2^T
        int u = t - 24576, n = u >> 7, k = u & 127;
        splitw(fW2[k * 128 + n], hi, lo);
        uint32_t o = n * PA + k * 2;
        *(__nv_bfloat16*)(d_wf2h + o) = hi;
        *(__nv_bfloat16*)(d_wf2l + o) = lo;
    }
}

__device__ __forceinline__ void cpa_block(uint32_t dst, const void* src, int size, int tid) {
    const char* s = (const char*)src;
    for (int o = tid * 16; o < size; o += 512 * 16) CP16(dst + o, s + o);
}

// ---------------------------------------------------------------------------
__global__ __launch_bounds__(512, 1)
void fused_gnn_kernel(const float* __restrict__ X,
                      const float* __restrict__ gW1,
                      const float* __restrict__ gb2, const float* __restrict__ gb3,
                      const float* __restrict__ fb2,
                      const float* __restrict__ fW3, const float* __restrict__ fb3,
                      float* __restrict__ out) {
    extern __shared__ char sm[];
    const uint32_t smb = smem_u32(sm);
    const int tid = threadIdx.x;
    const int wid = tid >> 5, lane = tid & 31;
    const int mw = wid & 7, nh = wid >> 3;
    const int m0 = mw * 16;
    const int row4 = tid >> 2, q = tid & 3;      // gen/agg: 4 threads per row

    float* sE   = (float*)(sm + OFF_E);
    float* sAdj = (float*)(sm + OFF_ADJ);
    float* sPart= (float*)(sm + OFF_PART);
    const uint32_t uAh = smb + OFF_AHI, uAl = smb + OFF_ALO;
    const uint32_t uWh = smb + OFF_W,   uWl = smb + OFF_W + 34816;
    const uint32_t uG3h = smb + OFF_G3, uG3l = smb + OFF_G3 + 8704;
    const uint32_t uF1h = smb + OFF_F1, uF1l = smb + OFF_F1 + 10240;
    char* sAh = sm + OFF_AHI;
    char* sAl = sm + OFF_ALO;

    // fragment->element mapping
    const int r0 = m0 + (lane >> 2), r1 = r0 + 8;
    const int c2 = 2 * (lane & 3);
    const int nc0 = nh * 64;

    // per-thread ldmatrix base offsets
    const uint32_t aOffA = (uint32_t)((m0 + (lane & 15)) * PA + (lane >> 4) * 16);
    const uint32_t aOffG = (uint32_t)((m0 + (lane & 15)) * PG + (lane >> 4) * 16);
    const uint32_t wrow  = (uint32_t)((lane & 7) + 8 * ((lane >> 3) & 1));
    const uint32_t wOffA = (uint32_t)((nc0 + wrow) * PA + (lane >> 4) * 16);
    const uint32_t wOffG = (uint32_t)((nc0 + wrow) * PG + (lane >> 4) * 16);
    const uint32_t wOffE = (uint32_t)((nh * 16 + wrow) * PA + (lane >> 4) * 16);

    // ---- prefetch: gW2 (group 0); gW3+fW1+fW3 resident (group 1) ----
    cpa_block(uWh, d_wg2h, 34816, tid);
    cpa_block(uWl, d_wg2l, 34816, tid);
    CP_COMMIT();
    cpa_block(uG3h, d_wg3h, 8704, tid);
    cpa_block(uG3l, d_wg3l, 8704, tid);
    cpa_block(uF1h, d_wf1h, 10240, tid);
    cpa_block(uF1l, d_wf1l, 10240, tid);
    cpa_block(smb + OFF_F3, fW3, 16384, tid);
    CP_COMMIT();

    // ---- stage 0/1: adj + h1 generation (overlaps prefetch) ----
    for (int idx = tid; idx < 1024; idx += 512)
        sAdj[(idx >> 5) * 33 + (idx & 31)] = d_wadjT[idx];
    {
        float xv = X[blockIdx.x * 128 + row4];
        int i = row4 & 31;
        const float* w1r = gW1 + i * 128;
        const float* cgr = d_cg + i * 128;
        #pragma unroll 8
        for (int kk = 0; kk < 32; kk += 2) {
            int k = q * 32 + kk;
            float h0 = lrelu(fmaf(xv, __ldg(w1r + k),     __ldg(cgr + k)));
            float h1v= lrelu(fmaf(xv, __ldg(w1r + k + 1), __ldg(cgr + k + 1)));
            __nv_bfloat162 vh, vl;
            splitw(h0,  vh.x, vl.x);
            splitw(h1v, vh.y, vl.y);
            *(__nv_bfloat162*)(sAh + row4 * PA + k * 2) = vh;
            *(__nv_bfloat162*)(sAl + row4 * PA + k * 2) = vl;
        }
    }
    CP_WAIT(1);                 // gW2 resident
    __syncthreads();            // B1: h1 + gW2 visible

    float C[8][4];

    // ---- stage 2: h2 = h1 + lrelu(h1 @ gW2 + gb2) ----
    #pragma unroll
    for (int n = 0; n < 8; ++n) { C[n][0] = C[n][1] = C[n][2] = C[n][3] = 0.f; }
    gemm_fused<8, 4, PA>(uAh + aOffA, uAl + aOffA, uWh + wOffA, uWl + wOffA, C);
    #pragma unroll
    for (int nt = 0; nt < 8; ++nt) {
        int col = nc0 + nt * 8 + c2;
        float b0 = __ldg(gb2 + col), b1 = __ldg(gb2 + col + 1);
        {
            __nv_bfloat162 hh = *(__nv_bfloat162*)(sAh + r0 * PA + col * 2);
            __nv_bfloat162 ll = *(__nv_bfloat162*)(sAl + r0 * PA + col * 2);
            float v0 = __bfloat162float(hh.x) + __bfloat162float(ll.x) + lrelu(C[nt][0] + b0);
            float v1 = __bfloat162float(hh.y) + __bfloat162float(ll.y) + lrelu(C[nt][1] + b1);
            __nv_bfloat162 vh, vl; splitw(v0, vh.x, vl.x); splitw(v1, vh.y, vl.y);
            *(__nv_bfloat162*)(sAh + r0 * PA + col * 2) = vh;
            *(__nv_bfloat162*)(sAl + r0 * PA + col * 2) = vl;
        }
        {
            __nv_bfloat162 hh = *(__nv_bfloat162*)(sAh + r1 * PA + col * 2);
            __nv_bfloat162 ll = *(__nv_bfloat162*)(sAl + r1 * PA + col * 2);
            float v0 = __bfloat162float(hh.x) + __bfloat162float(ll.x) + lrelu(C[nt][2] + b0);
            float v1 = __bfloat162float(hh.y) + __bfloat162float(ll.y) + lrelu(C[nt][3] + b1);
            __nv_bfloat162 vh, vl; splitw(v0, vh.x, vl.x); splitw(v1, vh.y, vl.y);
            *(__nv_bfloat162*)(sAh + r1 * PA + col * 2) = vh;
            *(__nv_bfloat162*)(sAl + r1 * PA + col * 2) = vl;
        }
    }
    CP_WAIT(0);                 // resident g3/f1/f3 landed
    __syncthreads();            // B2: h2 visible, sW (gW2) free

    // fW2 prefetch rides under stages 3-5 (group 2)
    cpa_block(uWh, d_wf2h, 34816, tid);
    cpa_block(uWl, d_wf2l, 34816, tid);
    CP_COMMIT();

    // ---- stage 3: e = h2 @ gW3 + gb3  (N=32 -> 1 pair/warp) ----
    #pragma unroll
    for (int n = 0; n < 2; ++n) { C[n][0] = C[n][1] = C[n][2] = C[n][3] = 0.f; }
    gemm_fused<8, 1, PA>(uAh + aOffA, uAl + aOffA, uG3h + wOffE, uG3l + wOffE, C);
    #pragma unroll
    for (int nt = 0; nt < 2; ++nt) {
        int col = nh * 16 + nt * 8 + c2;
        float b0 = __ldg(gb3 + col), b1 = __ldg(gb3 + col + 1);
        *(float2*)&sE[r0 * 36 + col] = make_float2(C[nt][0] + b0, C[nt][1] + b1);
        *(float2*)&sE[r1 * 36 + col] = make_float2(C[nt][2] + b0, C[nt][3] + b1);
    }
    __syncthreads();            // B3: sE complete, h2 no longer needed

    // ---- stage 4: aggregation -> split bf16 ag (pitch PG) ----
    {
        float acc[8];
        #pragma unroll
        for (int d = 0; d < 8; ++d) acc[d] = 0.f;
        int i = row4 & 31;
        int bbase = row4 & ~31;
        int dbase = q * 8;
        #pragma unroll 4
        for (int j = 0; j < 32; ++j) {
            float w = sAdj[i * 33 + j];
            const float* er = &sE[(bbase + j) * 36 + dbase];
            float4 e0 = *(const float4*)&er[0];
            float4 e1 = *(const float4*)&er[4];
            acc[0] = fmaf(w, e0.x, acc[0]); acc[1] = fmaf(w, e0.y, acc[1]);
            acc[2] = fmaf(w, e0.z, acc[2]); acc[3] = fmaf(w, e0.w, acc[3]);
            acc[4] = fmaf(w, e1.x, acc[4]); acc[5] = fmaf(w, e1.y, acc[5]);
            acc[6] = fmaf(w, e1.z, acc[6]); acc[7] = fmaf(w, e1.w, acc[7]);
        }
        #pragma unroll
        for (int d = 0; d < 8; d += 2) {
            int k = dbase + d;
            __nv_bfloat162 vh, vl;
            splitw(acc[d],     vh.x, vl.x);
            splitw(acc[d + 1], vh.y, vl.y);
            *(__nv_bfloat162*)(sAh + row4 * PG + k * 2) = vh;
            *(__nv_bfloat162*)(sAl + row4 * PG + k * 2) = vl;
        }
    }
    __syncthreads();            // B4: ag visible

    // ---- stage 5: p1 = lrelu(ag @ fW1 + c_f)  (K=32) ----
    #pragma unroll
    for (int n = 0; n < 8; ++n) { C[n][0] = C[n][1] = C[n][2] = C[n][3] = 0.f; }
    gemm_fused<2, 4, PG>(uAh + aOffG, uAl + aOffG, uF1h + wOffG, uF1l + wOffG, C);
    __syncthreads();            // B5: all warps done reading ag (PG layout)
    {
        const float* cf0 = d_cf + (r0 & 31) * 128;
        const float* cf1 = d_cf + (r1 & 31) * 128;
        #pragma unroll
        for (int nt = 0; nt < 8; ++nt) {
            int col = nc0 + nt * 8 + c2;
            float v0 = lrelu(C[nt][0] + __ldg(cf0 + col));
            float v1 = lrelu(C[nt][1] + __ldg(cf0 + col + 1));
            float v2 = lrelu(C[nt][2] + __ldg(cf1 + col));
            float v3 = lrelu(C[nt][3] + __ldg(cf1 + col + 1));
            __nv_bfloat162 vh, vl;
            splitw(v0, vh.x, vl.x); splitw(v1, vh.y, vl.y);
            *(__nv_bfloat162*)(sAh + r0 * PA + col * 2) = vh;
            *(__nv_bfloat162*)(sAl + r0 * PA + col * 2) = vl;
            splitw(v2, vh.x, vl.x); splitw(v3, vh.y, vl.y);
            *(__nv_bfloat162*)(sAh + r1 * PA + col * 2) = vh;
            *(__nv_bfloat162*)(sAl + r1 * PA + col * 2) = vl;
        }
    }
    CP_WAIT(0);                 // fW2 resident
    __syncthreads();            // B6: p1 visible + fW2 visible

    // ---- stage 6: p1 @ fW2 ----
    #pragma unroll
    for (int n = 0; n < 8; ++n) { C[n][0] = C[n][1] = C[n][2] = C[n][3] = 0.f; }
    gemm_fused<8, 4, PA>(uAh + aOffA, uAl + aOffA, uWh + wOffA, uWl + wOffA, C);

    // ---- stage 7: p2 + output dot (per-warp 64-col partial) ----
    {
        const float* sW3 = (const float*)(sm + OFF_F3);
        const int i0 = r0 & 31, i1 = r1 & 31;
        float acc0 = 0.f, acc1 = 0.f;
        #pragma unroll
        for (int nt = 0; nt < 8; ++nt) {
            int col = nc0 + nt * 8 + c2;
            float b0 = __ldg(fb2 + col), b1 = __ldg(fb2 + col + 1);
            {
                __nv_bfloat162 hh = *(__nv_bfloat162*)(sAh + r0 * PA + col * 2);
                __nv_bfloat162 ll = *(__nv_bfloat162*)(sAl + r0 * PA + col * 2);
                float p2a = __bfloat162float(hh.x) + __bfloat162float(ll.x) + lrelu(C[nt][0] + b0);
                float p2b = __bfloat162float(hh.y) + __bfloat162float(ll.y) + lrelu(C[nt][1] + b1);
                acc0 = fmaf(p2a, sW3[col * 32 + i0], acc0);
                acc0 = fmaf(p2b, sW3[(col + 1) * 32 + i0], acc0);
            }
            {
                __nv_bfloat162 hh = *(__nv_bfloat162*)(sAh + r1 * PA + col * 2);
                __nv_bfloat162 ll = *(__nv_bfloat162*)(sAl + r1 * PA + col * 2);
                float p2a = __bfloat162float(hh.x) + __bfloat162float(ll.x) + lrelu(C[nt][2] + b0);
                float p2b = __bfloat162float(hh.y) + __bfloat162float(ll.y) + lrelu(C[nt][3] + b1);
                acc1 = fmaf(p2a, sW3[col * 32 + i1], acc1);
                acc1 = fmaf(p2b, sW3[(col + 1) * 32 + i1], acc1);
            }
        }
        acc0 += __shfl_xor_sync(0xffffffffu, acc0, 1);
        acc0 += __shfl_xor_sync(0xffffffffu, acc0, 2);
        acc1 += __shfl_xor_sync(0xffffffffu, acc1, 1);
        acc1 += __shfl_xor_sync(0xffffffffu, acc1, 2);
        if ((lane & 3) == 0) {
            sPart[nh * 128 + r0] = acc0;
            sPart[nh * 128 + r1] = acc1;
        }
    }
    __syncthreads();            // B7
    if (tid < 128)
        out[blockIdx.x * 128 + tid] = sPart[tid] + sPart[128 + tid] + __ldg(fb3 + (tid & 31));
}

// ---------------------------------------------------------------------------
extern "C" void kernel_launch(void* const* d_in, const int* in_sizes, int n_in,
                              void* d_out, int out_size) {
    const float* X   = (const float*)d_in[0];
    const float* W   = (const float*)d_in[1];
    const float* emb = (const float*)d_in[2];
    const float* gW1 = (const float*)d_in[3];
    const float* gb1 = (const float*)d_in[4];
    const float* gW2 = (const float*)d_in[5];
    const float* gb2 = (const float*)d_in[6];
    const float* gW3 = (const float*)d_in[7];
    const float* gb3 = (const float*)d_in[8];
    const float* fW1 = (const float*)d_in[9];
    const float* fb1 = (const float*)d_in[10];
    const float* fW2 = (const float*)d_in[11];
    const float* fb2 = (const float*)d_in[12];
    const float* fW3 = (const float*)d_in[13];
    const float* fb3 = (const float*)d_in[14];
    float* out = (float*)d_out;

    int B = in_sizes[0] / 32;

    cudaFuncSetAttribute(fused_gnn_kernel,
                         cudaFuncAttributeMaxDynamicSharedMemorySize, SMEM_BYTES);

    setup_kernel<<<160, 256>>>(W, emb, gW1, gb1, gW2, gW3, fW1, fb1, fW2);
    fused_gnn_kernel<<<B / 4, 512, SMEM_BYTES>>>(X, gW1, gb2, gb3, fb2, fW3, fb3, out);
}

// round 8
// speedup vs baseline: 2.7220x; 1.8753x over previous
#include <cuda_runtime.h>
#include <cuda_bf16.h>
#include <cstdint>

// ---------------------------------------------------------------------------
// ContractiveInvertibleGNN — mma.sync bf16-split, 256-row CTA, 32x64 warp tiles.
// One SMEM region (WBUF) is time-multiplexed: gW2 -> {E | fW1 | gW3} -> fW2 -> fW3,
// refilled with cp.async right after each consumer barrier.
// ---------------------------------------------------------------------------

#define PA  272     // activation row pitch (128 bf16 + 16B pad)
#define PG  80      // ag row pitch (32 bf16 + pad)
#define PF1 80      // fW1 row pitch (32 bf16 + pad) — MUST be 16B multiple (ldmatrix)
#define PE  32      // e pitch in floats (128B)
#define PF3 36      // fW3 pitch in floats (144B)

#define OFF_AH   0          // 69632 = 256*272
#define OFF_AL   69632      // 69632
#define OFF_W    139264     // 70656: gW2(hi|lo) -> {E | F1 | G3} -> fW2 -> F3
#define OFF_ADJ  209920     // 4224 (33*32*4)
#define OFF_PART 214144     // 2048 (sX early, partials late)
#define SMEM_BYTES 216192

#define W_E   0             // 32768 (256*128)
#define W_F1  32768         // 20480 (2*10240)
#define W_G3  53248         // 17408 (2*8704)

// ---- preformatted weights ----
__device__ __align__(256) char d_wg2h[34816], d_wg2l[34816]; // [n128][k128] p272
__device__ __align__(256) char d_wg3h[8704],  d_wg3l[8704];  // [n32][k128]  p272
__device__ __align__(256) char d_wf1h[10240], d_wf1l[10240]; // [n128][k32]  p80
__device__ __align__(256) char d_wf2h[34816], d_wf2l[34816]; // [n128][k128] p272
__device__ float d_cg[4096], d_cf[4096], d_wadjT[1024];

__device__ __forceinline__ float lrelu(float x) { return x > 0.f ? x : 0.01f * x; }
__device__ __forceinline__ void splitw(float w, __nv_bfloat16& hi, __nv_bfloat16& lo) {
    hi = __float2bfloat16(w);
    lo = __float2bfloat16(w - __bfloat162float(hi));
}
__device__ __forceinline__ uint32_t smem_u32(const void* p) {
    uint32_t a;
    asm("{ .reg .u64 t; cvta.to.shared.u64 t, %1; cvt.u32.u64 %0, t; }" : "=r"(a) : "l"(p));
    return a;
}

#define LDSM_X4(r0, r1, r2, r3, addr)                                        \
    asm volatile("ldmatrix.sync.aligned.m8n8.x4.shared.b16 {%0,%1,%2,%3}, [%4];" \
                 : "=r"(r0), "=r"(r1), "=r"(r2), "=r"(r3) : "r"(addr))
#define CP16(d, s) \
    asm volatile("cp.async.ca.shared.global [%0], [%1], 16;" \
                 :: "r"(d), "l"((unsigned long long)__cvta_generic_to_global(s)) : "memory")
#define CP_COMMIT() asm volatile("cp.async.commit_group;" ::: "memory")
#define CP_WAIT0()  asm volatile("cp.async.wait_group 0;" ::: "memory")

__device__ __forceinline__ void mma16816(float* c, const uint32_t* a,
                                         uint32_t b0, uint32_t b1) {
    asm volatile("mma.sync.aligned.m16n8k16.row.col.f32.bf16.bf16.f32 "
                 "{%0,%1,%2,%3}, {%4,%5,%6,%7}, {%8,%9}, {%0,%1,%2,%3};"
                 : "+f"(c[0]), "+f"(c[1]), "+f"(c[2]), "+f"(c[3])
                 : "r"(a[0]), "r"(a[1]), "r"(a[2]), "r"(a[3]), "r"(b0), "r"(b1));
}

// 2-m-tile fused 3-term split GEMM. Always takes C[2][8][4]; only the first
// 2*NPAIR n-tiles per m-tile are touched.
template <int KS, int NPAIR, int AP, int WP>
__device__ __forceinline__ void gemm_2m(uint32_t aH, uint32_t aL,
                                        uint32_t wH, uint32_t wL,
                                        float C[2][8][4]) {
    #pragma unroll
    for (int k = 0; k < KS; ++k) {
        uint32_t ah[2][4], al[2][4];
        LDSM_X4(ah[0][0], ah[0][1], ah[0][2], ah[0][3], aH + k * 32);
        LDSM_X4(ah[1][0], ah[1][1], ah[1][2], ah[1][3], aH + 16 * AP + k * 32);
        LDSM_X4(al[0][0], al[0][1], al[0][2], al[0][3], aL + k * 32);
        LDSM_X4(al[1][0], al[1][1], al[1][2], al[1][3], aL + 16 * AP + k * 32);
        #pragma unroll
        for (int p = 0; p < NPAIR; ++p) {
            uint32_t bh0, bh1, bh2, bh3, bl0, bl1, bl2, bl3;
            LDSM_X4(bh0, bh1, bh2, bh3, wH + p * 16 * WP + k * 32);
            LDSM_X4(bl0, bl1, bl2, bl3, wL + p * 16 * WP + k * 32);
            #pragma unroll
            for (int t = 0; t < 2; ++t) {
                mma16816(C[t][2 * p],     ah[t], bh0, bh2);
                mma16816(C[t][2 * p + 1], ah[t], bh1, bh3);
                mma16816(C[t][2 * p],     al[t], bh0, bh2);
                mma16816(C[t][2 * p + 1], al[t], bh1, bh3);
                mma16816(C[t][2 * p],     ah[t], bl0, bl2);
                mma16816(C[t][2 * p + 1], ah[t], bl1, bl3);
            }
        }
    }
}

// ---------------------------------------------------------------------------
__global__ void setup_kernel(const float* __restrict__ W, const float* __restrict__ emb,
                             const float* __restrict__ gW1, const float* __restrict__ gb1,
                             const float* __restrict__ gW2, const float* __restrict__ gW3,
                             const float* __restrict__ fW1, const float* __restrict__ fb1,
                             const float* __restrict__ fW2) {
    int t = blockIdx.x * blockDim.x + threadIdx.x;
    if (t < 4096) {
        int i = t >> 7, a = t & 127;
        float sg = gb1[a], sf = fb1[a];
        #pragma unroll
        for (int e = 0; e < 32; ++e) {
            float em = emb[i * 32 + e];
            sg = fmaf(em, gW1[(32 + e) * 128 + a], sg);
            sf = fmaf(em, fW1[(32 + e) * 128 + a], sf);
        }
        d_cg[t] = sg;
        d_cf[t] = sf;
    }
    if (t < 1024) {
        int i = t >> 5, j = t & 31;
        d_wadjT[t] = (i == j) ? 0.f : W[j * 32 + i];
    }
    __nv_bfloat16 hi, lo;
    if (t < 16384) {                       // gW2^T
        int n = t >> 7, k = t & 127;
        splitw(gW2[k * 128 + n], hi, lo);
        uint32_t o = n * PA + k * 2;
        *(__nv_bfloat16*)(d_wg2h + o) = hi;
        *(__nv_bfloat16*)(d_wg2l + o) = lo;
    } else if (t < 20480) {                // gW3^T
        int u = t - 16384, n = u >> 7, k = u & 127;
        splitw(gW3[k * 32 + n], hi, lo);
        uint32_t o = n * PA + k * 2;
        *(__nv_bfloat16*)(d_wg3h + o) = hi;
        *(__nv_bfloat16*)(d_wg3l + o) = lo;
    } else if (t < 24576) {                // fW1[:32]^T
        int u = t - 20480, n = u >> 5, k = u & 31;
        splitw(fW1[k * 128 + n], hi, lo);
        uint32_t o = n * PF1 + k * 2;
        *(__nv_bfloat16*)(d_wf1h + o) = hi;
        *(__nv_bfloat16*)(d_wf1l + o) = lo;
    } else if (t < 40960) {                // fW2^T
        int u = t - 24576, n = u >> 7, k = u & 127;
        splitw(fW2[k * 128 + n], hi, lo);
        uint32_t o = n * PA + k * 2;
        *(__nv_bfloat16*)(d_wf2h + o) = hi;
        *(__nv_bfloat16*)(d_wf2l + o) = lo;
    }
}

__device__ __forceinline__ void cpa(uint32_t dst, const void* src, int size, int tid) {
    const char* s = (const char*)src;
    for (int o = tid * 16; o < size; o += 512 * 16) CP16(dst + o, s + o);
}

// ---------------------------------------------------------------------------
__global__ __launch_bounds__(512, 1)
void fused_gnn_kernel(const float* __restrict__ X,
                      const float* __restrict__ gW1,
                      const float* __restrict__ gb2, const float* __restrict__ gb3,
                      const float* __restrict__ fb2,
                      const float* __restrict__ fW3, const float* __restrict__ fb3,
                      float* __restrict__ out) {
    extern __shared__ char sm[];
    const uint32_t smb = smem_u32(sm);
    const int tid = threadIdx.x;
    const int wid = tid >> 5, lane = tid & 31;
    const int mw = wid & 7, nh = wid >> 3;
    const int m0 = mw * 32;
    const int rowH = tid >> 1, hf = tid & 1;

    char*  sAh  = sm + OFF_AH;
    char*  sAl  = sm + OFF_AL;
    float* sE   = (float*)(sm + OFF_W + W_E);
    float* sAdj = (float*)(sm + OFF_ADJ);
    float* sPx  = (float*)(sm + OFF_PART);   // sX early, partials late
    const uint32_t uAh = smb + OFF_AH, uAl = smb + OFF_AL;
    const uint32_t uW = smb + OFF_W;

    const int r0 = m0 + (lane >> 2);
    const int c2 = 2 * (lane & 3);
    const int nc0 = nh * 64;

    const uint32_t aOffA = (uint32_t)((m0 + (lane & 15)) * PA + (lane >> 4) * 16);
    const uint32_t aOffG = (uint32_t)((m0 + (lane & 15)) * PG + (lane >> 4) * 16);
    const uint32_t wrow  = (uint32_t)((lane & 7) + 8 * ((lane >> 3) & 1));
    const uint32_t wOffA  = (uint32_t)((nc0 + wrow) * PA + (lane >> 4) * 16);
    const uint32_t wOffG3 = (uint32_t)((nh * 16 + wrow) * PA + (lane >> 4) * 16);
    const uint32_t wOffF1 = (uint32_t)((nc0 + wrow) * PF1 + (lane >> 4) * 16);

    // ---- prologue: gW2 prefetch (G0) + X/adj staging ----
    cpa(uW, d_wg2h, 34816, tid);
    cpa(uW + 34816, d_wg2l, 34816, tid);
    CP_COMMIT();
    if (tid < 256) sPx[tid] = X[blockIdx.x * 256 + tid];
    for (int idx = tid; idx < 1024; idx += 512)
        sAdj[(idx >> 5) * 33 + (idx & 31)] = d_wadjT[idx];
    __syncthreads();                                   // B0: sX visible

    // ---- stage 1: h1. thread = (i, k-chunk) x 8 batches ----
    {
        int i = tid & 31, kc = tid >> 5;               // kc 0..15
        float w1v[8], cgv[8];
        #pragma unroll
        for (int u = 0; u < 8; ++u) {
            int k = kc * 8 + u;
            w1v[u] = __ldg(gW1 + i * 128 + k);
            cgv[u] = __ldg(d_cg + i * 128 + k);
        }
        #pragma unroll
        for (int b = 0; b < 8; ++b) {
            int row = b * 32 + i;
            float xv = sPx[row];
            #pragma unroll
            for (int u = 0; u < 8; u += 2) {
                int k = kc * 8 + u;
                float h0 = lrelu(fmaf(xv, w1v[u],     cgv[u]));
                float h1v= lrelu(fmaf(xv, w1v[u + 1], cgv[u + 1]));
                __nv_bfloat162 vh, vl;
                splitw(h0,  vh.x, vl.x);
                splitw(h1v, vh.y, vl.y);
                *(__nv_bfloat162*)(sAh + row * PA + k * 2) = vh;
                *(__nv_bfloat162*)(sAl + row * PA + k * 2) = vl;
            }
        }
    }
    CP_WAIT0();
    __syncthreads();                                   // B1: h1 + gW2

    float C[2][8][4];

    // ---- stage 2: h2 = h1 + lrelu(h1 @ gW2 + gb2) ----
    #pragma unroll
    for (int t = 0; t < 2; ++t)
        #pragma unroll
        for (int n = 0; n < 8; ++n)
            C[t][n][0] = C[t][n][1] = C[t][n][2] = C[t][n][3] = 0.f;
    gemm_2m<8, 4, PA, PA>(uAh + aOffA, uAl + aOffA, uW + wOffA, uW + 34816 + wOffA, C);
    __syncthreads();                                   // B2a: gW2 dead
    cpa(uW + W_F1, d_wf1h, 10240, tid);
    cpa(uW + W_F1 + 10240, d_wf1l, 10240, tid);
    cpa(uW + W_G3, d_wg3h, 8704, tid);
    cpa(uW + W_G3 + 8704, d_wg3l, 8704, tid);
    CP_COMMIT();                                       // G1 under epilogue
    #pragma unroll
    for (int t = 0; t < 2; ++t) {
        int ra = r0 + 16 * t, rb = ra + 8;
        #pragma unroll
        for (int nt = 0; nt < 8; ++nt) {
            int col = nc0 + nt * 8 + c2;
            float b0 = __ldg(gb2 + col), b1 = __ldg(gb2 + col + 1);
            {
                __nv_bfloat162 hh = *(__nv_bfloat162*)(sAh + ra * PA + col * 2);
                __nv_bfloat162 ll = *(__nv_bfloat162*)(sAl + ra * PA + col * 2);
                float v0 = __bfloat162float(hh.x) + __bfloat162float(ll.x) + lrelu(C[t][nt][0] + b0);
                float v1 = __bfloat162float(hh.y) + __bfloat162float(ll.y) + lrelu(C[t][nt][1] + b1);
                __nv_bfloat162 vh, vl; splitw(v0, vh.x, vl.x); splitw(v1, vh.y, vl.y);
                *(__nv_bfloat162*)(sAh + ra * PA + col * 2) = vh;
                *(__nv_bfloat162*)(sAl + ra * PA + col * 2) = vl;
            }
            {
                __nv_bfloat162 hh = *(__nv_bfloat162*)(sAh + rb * PA + col * 2);
                __nv_bfloat162 ll = *(__nv_bfloat162*)(sAl + rb * PA + col * 2);
                float v0 = __bfloat162float(hh.x) + __bfloat162float(ll.x) + lrelu(C[t][nt][2] + b0);
                float v1 = __bfloat162float(hh.y) + __bfloat162float(ll.y) + lrelu(C[t][nt][3] + b1);
                __nv_bfloat162 vh, vl; splitw(v0, vh.x, vl.x); splitw(v1, vh.y, vl.y);
                *(__nv_bfloat162*)(sAh + rb * PA + col * 2) = vh;
                *(__nv_bfloat162*)(sAl + rb * PA + col * 2) = vl;
            }
        }
    }
    CP_WAIT0();
    __syncthreads();                                   // B2b: h2 + G3/F1

    // ---- stage 3: e = h2 @ gW3 + gb3 (N=32 -> 1 pair per nh) ----
    #pragma unroll
    for (int t = 0; t < 2; ++t)
        #pragma unroll
        for (int n = 0; n < 2; ++n)
            C[t][n][0] = C[t][n][1] = C[t][n][2] = C[t][n][3] = 0.f;
    gemm_2m<8, 1, PA, PA>(uAh + aOffA, uAl + aOffA,
                          uW + W_G3 + wOffG3, uW + W_G3 + 8704 + wOffG3, C);
    #pragma unroll
    for (int t = 0; t < 2; ++t) {
        int ra = r0 + 16 * t, rb = ra + 8;
        #pragma unroll
        for (int nt = 0; nt < 2; ++nt) {
            int col = nh * 16 + nt * 8 + c2;
            float b0 = __ldg(gb3 + col), b1 = __ldg(gb3 + col + 1);
            *(float2*)&sE[ra * PE + col] = make_float2(C[t][nt][0] + b0, C[t][nt][1] + b1);
            *(float2*)&sE[rb * PE + col] = make_float2(C[t][nt][2] + b0, C[t][nt][3] + b1);
        }
    }
    __syncthreads();                                   // B3: sE done, h2/A free

    // ---- stage 4: aggregation -> ag split bf16 (PG) ----
    {
        float acc[16];
        #pragma unroll
        for (int d = 0; d < 16; ++d) acc[d] = 0.f;
        int i = rowH & 31;
        int bbase = rowH & ~31;
        #pragma unroll 4
        for (int j = 0; j < 32; ++j) {
            float w = sAdj[i * 33 + j];
            const float* er = &sE[(bbase + j) * PE + hf * 16];
            #pragma unroll
            for (int qq = 0; qq < 4; ++qq) {
                float4 ev = *(const float4*)&er[qq * 4];
                acc[qq * 4 + 0] = fmaf(w, ev.x, acc[qq * 4 + 0]);
                acc[qq * 4 + 1] = fmaf(w, ev.y, acc[qq * 4 + 1]);
                acc[qq * 4 + 2] = fmaf(w, ev.z, acc[qq * 4 + 2]);
                acc[qq * 4 + 3] = fmaf(w, ev.w, acc[qq * 4 + 3]);
            }
        }
        #pragma unroll
        for (int d = 0; d < 16; d += 2) {
            int k = hf * 16 + d;
            __nv_bfloat162 vh, vl;
            splitw(acc[d],     vh.x, vl.x);
            splitw(acc[d + 1], vh.y, vl.y);
            *(__nv_bfloat162*)(sAh + rowH * PG + k * 2) = vh;
            *(__nv_bfloat162*)(sAl + rowH * PG + k * 2) = vl;
        }
    }
    __syncthreads();                                   // B4: ag visible

    // ---- stage 5: p1 = lrelu(ag @ fW1 + c_f) (K=32) ----
    #pragma unroll
    for (int t = 0; t < 2; ++t)
        #pragma unroll
        for (int n = 0; n < 8; ++n)
            C[t][n][0] = C[t][n][1] = C[t][n][2] = C[t][n][3] = 0.f;
    gemm_2m<2, 4, PG, PF1>(uAh + aOffG, uAl + aOffG,
                           uW + W_F1 + wOffF1, uW + W_F1 + 10240 + wOffF1, C);
    __syncthreads();                                   // B5a: ag/F1/E dead
    cpa(uW, d_wf2h, 34816, tid);
    cpa(uW + 34816, d_wf2l, 34816, tid);
    CP_COMMIT();                                       // G2 under epilogue
    #pragma unroll
    for (int t = 0; t < 2; ++t) {
        int ra = r0 + 16 * t, rb = ra + 8;
        const float* cfa = d_cf + (ra & 31) * 128;
        const float* cfb = d_cf + (rb & 31) * 128;
        #pragma unroll
        for (int nt = 0; nt < 8; ++nt) {
            int col = nc0 + nt * 8 + c2;
            float v0 = lrelu(C[t][nt][0] + __ldg(cfa + col));
            float v1 = lrelu(C[t][nt][1] + __ldg(cfa + col + 1));
            float v2 = lrelu(C[t][nt][2] + __ldg(cfb + col));
            float v3 = lrelu(C[t][nt][3] + __ldg(cfb + col + 1));
            __nv_bfloat162 vh, vl;
            splitw(v0, vh.x, vl.x); splitw(v1, vh.y, vl.y);
            *(__nv_bfloat162*)(sAh + ra * PA + col * 2) = vh;
            *(__nv_bfloat162*)(sAl + ra * PA + col * 2) = vl;
            splitw(v2, vh.x, vl.x); splitw(v3, vh.y, vl.y);
            *(__nv_bfloat162*)(sAh + rb * PA + col * 2) = vh;
            *(__nv_bfloat162*)(sAl + rb * PA + col * 2) = vl;
        }
    }
    CP_WAIT0();
    __syncthreads();                                   // B5b: p1 + fW2

    // ---- stage 6: p1 @ fW2 ----
    #pragma unroll
    for (int t = 0; t < 2; ++t)
        #pragma unroll
        for (int n = 0; n < 8; ++n)
            C[t][n][0] = C[t][n][1] = C[t][n][2] = C[t][n][3] = 0.f;
    gemm_2m<8, 4, PA, PA>(uAh + aOffA, uAl + aOffA, uW + wOffA, uW + 34816 + wOffA, C);
    __syncthreads();                                   // B6a: fW2 dead
    // F3 repack fp32 [a=128][i=32] -> pitch 36 floats
    for (int idx = tid; idx < 1024; idx += 512) {
        int a = idx >> 3, c = idx & 7;
        CP16(uW + a * (PF3 * 4) + c * 16, fW3 + a * 32 + c * 4);
    }
    CP_COMMIT();

    // ---- stage 7a: p2 into C (overlaps F3 flight) ----
    #pragma unroll
    for (int t = 0; t < 2; ++t) {
        int ra = r0 + 16 * t, rb = ra + 8;
        #pragma unroll
        for (int nt = 0; nt < 8; ++nt) {
            int col = nc0 + nt * 8 + c2;
            float b0 = __ldg(fb2 + col), b1 = __ldg(fb2 + col + 1);
            __nv_bfloat162 hh = *(__nv_bfloat162*)(sAh + ra * PA + col * 2);
            __nv_bfloat162 ll = *(__nv_bfloat162*)(sAl + ra * PA + col * 2);
            C[t][nt][0] = __bfloat162float(hh.x) + __bfloat162float(ll.x) + lrelu(C[t][nt][0] + b0);
            C[t][nt][1] = __bfloat162float(hh.y) + __bfloat162float(ll.y) + lrelu(C[t][nt][1] + b1);
            hh = *(__nv_bfloat162*)(sAh + rb * PA + col * 2);
            ll = *(__nv_bfloat162*)(sAl + rb * PA + col * 2);
            C[t][nt][2] = __bfloat162float(hh.x) + __bfloat162float(ll.x) + lrelu(C[t][nt][2] + b0);
            C[t][nt][3] = __bfloat162float(hh.y) + __bfloat162float(ll.y) + lrelu(C[t][nt][3] + b1);
        }
    }
    CP_WAIT0();
    __syncthreads();                                   // B6b: F3 visible

    // ---- stage 7b: dot with fW3, reduce, partials ----
    {
        const float* sW3 = (const float*)(sm + OFF_W);
        float acc[2][2] = {{0.f, 0.f}, {0.f, 0.f}};
        #pragma unroll
        for (int t = 0; t < 2; ++t) {
            int ra = r0 + 16 * t, rb = ra + 8;
            int ia = ra & 31, ib = rb & 31;
            #pragma unroll
            for (int nt = 0; nt < 8; ++nt) {
                int col = nc0 + nt * 8 + c2;
                acc[t][0] = fmaf(C[t][nt][0], sW3[col * PF3 + ia], acc[t][0]);
                acc[t][0] = fmaf(C[t][nt][1], sW3[(col + 1) * PF3 + ia], acc[t][0]);
                acc[t][1] = fmaf(C[t][nt][2], sW3[col * PF3 + ib], acc[t][1]);
                acc[t][1] = fmaf(C[t][nt][3], sW3[(col + 1) * PF3 + ib], acc[t][1]);
            }
        }
        #pragma unroll
        for (int t = 0; t < 2; ++t) {
            acc[t][0] += __shfl_xor_sync(0xffffffffu, acc[t][0], 1);
            acc[t][0] += __shfl_xor_sync(0xffffffffu, acc[t][0], 2);
            acc[t][1] += __shfl_xor_sync(0xffffffffu, acc[t][1], 1);
            acc[t][1] += __shfl_xor_sync(0xffffffffu, acc[t][1], 2);
        }
        __syncthreads();                               // sPx: sX -> partials
        if ((lane & 3) == 0) {
            #pragma unroll
            for (int t = 0; t < 2; ++t) {
                sPx[nh * 256 + r0 + 16 * t]     = acc[t][0];
                sPx[nh * 256 + r0 + 16 * t + 8] = acc[t][1];
            }
        }
    }
    __syncthreads();                                   // B7
    if (tid < 256)
        out[blockIdx.x * 256 + tid] = sPx[tid] + sPx[256 + tid] + __ldg(fb3 + (tid & 31));
}

// ---------------------------------------------------------------------------
extern "C" void kernel_launch(void* const* d_in, const int* in_sizes, int n_in,
                              void* d_out, int out_size) {
    const float* X   = (const float*)d_in[0];
    const float* W   = (const float*)d_in[1];
    const float* emb = (const float*)d_in[2];
    const float* gW1 = (const float*)d_in[3];
    const float* gb1 = (const float*)d_in[4];
    const float* gW2 = (const float*)d_in[5];
    const float* gb2 = (const float*)d_in[6];
    const float* gW3 = (const float*)d_in[7];
    const float* gb3 = (const float*)d_in[8];
    const float* fW1 = (const float*)d_in[9];
    const float* fb1 = (const float*)d_in[10];
    const float* fW2 = (const float*)d_in[11];
    const float* fb2 = (const float*)d_in[12];
    const float* fW3 = (const float*)d_in[13];
    const float* fb3 = (const float*)d_in[14];
    float* out = (float*)d_out;

    int B = in_sizes[0] / 32;

    cudaFuncSetAttribute(fused_gnn_kernel,
                         cudaFuncAttributeMaxDynamicSharedMemorySize, SMEM_BYTES);

    setup_kernel<<<160, 256>>>(W, emb, gW1, gb1, gW2, gW3, fW1, fb1, fW2);
    fused_gnn_kernel<<<B / 8, 512, SMEM_BYTES>>>(X, gW1, gb2, gb3, fb2, fW3, fb3, out);
}

// round 10
// speedup vs baseline: 3.4435x; 1.2651x over previous
#include <cuda_runtime.h>
#include <cuda_fp16.h>
#include <cstdint>

// ---------------------------------------------------------------------------
// ContractiveInvertibleGNN — mma.sync fp16 2-term split, 256-row CTA,
// 32x64 warp tiles. Terms: Ahi*Bhi + Alo*Bhi (B quantization error 2^-12,
// predicted rel_err ~4e-4 vs 1e-3 gate). Weights fp16 hi only.
// SMEM W region time-multiplexed: gW2 -> {E | fW1 | gW3} -> fW2 -> fW3.
// ---------------------------------------------------------------------------

#define PA  272     // activation row pitch (128 fp16 + 16B pad)
#define PG  80      // ag row pitch (32 fp16 + pad)
#define PF1 80      // fW1 row pitch — 16B multiple (ldmatrix)
#define PE  32      // e pitch in floats (128B)
#define PF3 36      // fW3 pitch in floats (144B)

#define OFF_AH   0          // 69632 = 256*272
#define OFF_AL   69632      // 69632
#define OFF_W    139264     // 51712: gW2(hi) -> {E | F1 | G3} -> fW2 -> F3
#define OFF_ADJ  190976     // 4224 (33*32*4)
#define OFF_PART 195200     // 2048 (sX early, partials late)
#define SMEM_BYTES 197248

#define W_E   0             // 32768 (256 rows * 128B)
#define W_F1  32768         // 10240
#define W_G3  43008         // 8704

// ---- preformatted fp16 weights ----
__device__ __align__(256) char d_wg2h[34816];  // gW2^T [n128][k128] p272
__device__ __align__(256) char d_wg3h[8704];   // gW3^T [n32][k128]  p272
__device__ __align__(256) char d_wf1h[10240];  // fW1^T [n128][k32]  p80
__device__ __align__(256) char d_wf2h[34816];  // fW2^T [n128][k128] p272
__device__ float d_cg[4096], d_cf[4096], d_wadjT[1024];

__device__ __forceinline__ float lrelu(float x) { return x > 0.f ? x : 0.01f * x; }
__device__ __forceinline__ void splitw(float w, __half& hi, __half& lo) {
    hi = __float2half_rn(w);
    lo = __float2half_rn(w - __half2float(hi));
}
__device__ __forceinline__ uint32_t smem_u32(const void* p) {
    uint32_t a;
    asm("{ .reg .u64 t; cvta.to.shared.u64 t, %1; cvt.u32.u64 %0, t; }" : "=r"(a) : "l"(p));
    return a;
}

#define LDSM_X4(r0, r1, r2, r3, addr)                                        \
    asm volatile("ldmatrix.sync.aligned.m8n8.x4.shared.b16 {%0,%1,%2,%3}, [%4];" \
                 : "=r"(r0), "=r"(r1), "=r"(r2), "=r"(r3) : "r"(addr))
#define CP16(d, s) \
    asm volatile("cp.async.ca.shared.global [%0], [%1], 16;" \
                 :: "r"(d), "l"((unsigned long long)__cvta_generic_to_global(s)) : "memory")
#define CP_COMMIT() asm volatile("cp.async.commit_group;" ::: "memory")
#define CP_WAIT0()  asm volatile("cp.async.wait_group 0;" ::: "memory")

__device__ __forceinline__ void mma16816(float* c, const uint32_t* a,
                                         uint32_t b0, uint32_t b1) {
    asm volatile("mma.sync.aligned.m16n8k16.row.col.f32.f16.f16.f32 "
                 "{%0,%1,%2,%3}, {%4,%5,%6,%7}, {%8,%9}, {%0,%1,%2,%3};"
                 : "+f"(c[0]), "+f"(c[1]), "+f"(c[2]), "+f"(c[3])
                 : "r"(a[0]), "r"(a[1]), "r"(a[2]), "r"(a[3]), "r"(b0), "r"(b1));
}

// 2-m-tile 2-term split GEMM: C += (Ahi + Alo) @ Bhi. C[2][8][4]; only the
// first 2*NPAIR n-tiles per m-tile are touched.
template <int KS, int NPAIR, int AP, int WP>
__device__ __forceinline__ void gemm_2m(uint32_t aH, uint32_t aL, uint32_t wH,
                                        float C[2][8][4]) {
    #pragma unroll
    for (int k = 0; k < KS; ++k) {
        uint32_t ah[2][4], al[2][4];
        LDSM_X4(ah[0][0], ah[0][1], ah[0][2], ah[0][3], aH + k * 32);
        LDSM_X4(ah[1][0], ah[1][1], ah[1][2], ah[1][3], aH + 16 * AP + k * 32);
        LDSM_X4(al[0][0], al[0][1], al[0][2], al[0][3], aL + k * 32);
        LDSM_X4(al[1][0], al[1][1], al[1][2], al[1][3], aL + 16 * AP + k * 32);
        #pragma unroll
        for (int p = 0; p < NPAIR; ++p) {
            uint32_t bh0, bh1, bh2, bh3;
            LDSM_X4(bh0, bh1, bh2, bh3, wH + p * 16 * WP + k * 32);
            #pragma unroll
            for (int t = 0; t < 2; ++t) {
                mma16816(C[t][2 * p],     ah[t], bh0, bh2);
                mma16816(C[t][2 * p + 1], ah[t], bh1, bh3);
                mma16816(C[t][2 * p],     al[t], bh0, bh2);
                mma16816(C[t][2 * p + 1], al[t], bh1, bh3);
            }
        }
    }
}

// ---------------------------------------------------------------------------
__global__ void setup_kernel(const float* __restrict__ W, const float* __restrict__ emb,
                             const float* __restrict__ gW1, const float* __restrict__ gb1,
                             const float* __restrict__ gW2, const float* __restrict__ gW3,
                             const float* __restrict__ fW1, const float* __restrict__ fb1,
                             const float* __restrict__ fW2) {
    int t = blockIdx.x * blockDim.x + threadIdx.x;
    if (t < 4096) {
        int i = t >> 7, a = t & 127;
        float sg = gb1[a], sf = fb1[a];
        #pragma unroll
        for (int e = 0; e < 32; ++e) {
            float em = emb[i * 32 + e];
            sg = fmaf(em, gW1[(32 + e) * 128 + a], sg);
            sf = fmaf(em, fW1[(32 + e) * 128 + a], sf);
        }
        d_cg[t] = sg;
        d_cf[t] = sf;
    }
    if (t < 1024) {
        int i = t >> 5, j = t & 31;
        d_wadjT[t] = (i == j) ? 0.f : W[j * 32 + i];
    }
    if (t < 16384) {                       // gW2^T
        int n = t >> 7, k = t & 127;
        *(__half*)(d_wg2h + n * PA + k * 2) = __float2half_rn(gW2[k * 128 + n]);
    } else if (t < 20480) {                // gW3^T
        int u = t - 16384, n = u >> 7, k = u & 127;
        *(__half*)(d_wg3h + n * PA + k * 2) = __float2half_rn(gW3[k * 32 + n]);
    } else if (t < 24576) {                // fW1[:32]^T
        int u = t - 20480, n = u >> 5, k = u & 31;
        *(__half*)(d_wf1h + n * PF1 + k * 2) = __float2half_rn(fW1[k * 128 + n]);
    } else if (t < 40960) {                // fW2^T
        int u = t - 24576, n = u >> 7, k = u & 127;
        *(__half*)(d_wf2h + n * PA + k * 2) = __float2half_rn(fW2[k * 128 + n]);
    }
}

__device__ __forceinline__ void cpa(uint32_t dst, const void* src, int size, int tid) {
    const char* s = (const char*)src;
    for (int o = tid * 16; o < size; o += 512 * 16) CP16(dst + o, s + o);
}

// ---------------------------------------------------------------------------
__global__ __launch_bounds__(512, 1)
void fused_gnn_kernel(const float* __restrict__ X,
                      const float* __restrict__ gW1,
                      const float* __restrict__ gb2, const float* __restrict__ gb3,
                      const float* __restrict__ fb2,
                      const float* __restrict__ fW3, const float* __restrict__ fb3,
                      float* __restrict__ out) {
    extern __shared__ char sm[];
    const uint32_t smb = smem_u32(sm);
    const int tid = threadIdx.x;
    const int wid = tid >> 5, lane = tid & 31;
    const int mw = wid & 7, nh = wid >> 3;
    const int m0 = mw * 32;
    const int rowH = tid >> 1, hf = tid & 1;

    char*  sAh  = sm + OFF_AH;
    char*  sAl  = sm + OFF_AL;
    float* sE   = (float*)(sm + OFF_W + W_E);
    float* sAdj = (float*)(sm + OFF_ADJ);
    float* sPx  = (float*)(sm + OFF_PART);   // sX early, partials late
    const uint32_t uAh = smb + OFF_AH, uAl = smb + OFF_AL;
    const uint32_t uW = smb + OFF_W;

    const int r0 = m0 + (lane >> 2);
    const int c2 = 2 * (lane & 3);
    const int nc0 = nh * 64;

    const uint32_t aOffA = (uint32_t)((m0 + (lane & 15)) * PA + (lane >> 4) * 16);
    const uint32_t aOffG = (uint32_t)((m0 + (lane & 15)) * PG + (lane >> 4) * 16);
    const uint32_t wrow  = (uint32_t)((lane & 7) + 8 * ((lane >> 3) & 1));
    const uint32_t wOffA  = (uint32_t)((nc0 + wrow) * PA + (lane >> 4) * 16);
    const uint32_t wOffG3 = (uint32_t)((nh * 16 + wrow) * PA + (lane >> 4) * 16);
    const uint32_t wOffF1 = (uint32_t)((nc0 + wrow) * PF1 + (lane >> 4) * 16);

    // ---- prologue: gW2 prefetch (G0) + X/adj staging ----
    cpa(uW, d_wg2h, 34816, tid);
    CP_COMMIT();
    if (tid < 256) sPx[tid] = X[blockIdx.x * 256 + tid];
    for (int idx = tid; idx < 1024; idx += 512)
        sAdj[(idx >> 5) * 33 + (idx & 31)] = d_wadjT[idx];
    __syncthreads();                                   // B0: sX visible

    // ---- stage 1: h1. thread = (i, k-chunk) x 8 batches ----
    {
        int i = tid & 31, kc = tid >> 5;               // kc 0..15
        float w1v[8], cgv[8];
        #pragma unroll
        for (int u = 0; u < 8; ++u) {
            int k = kc * 8 + u;
            w1v[u] = __ldg(gW1 + i * 128 + k);
            cgv[u] = __ldg(d_cg + i * 128 + k);
        }
        #pragma unroll
        for (int b = 0; b < 8; ++b) {
            int row = b * 32 + i;
            float xv = sPx[row];
            #pragma unroll
            for (int u = 0; u < 8; u += 2) {
                int k = kc * 8 + u;
                float h0 = lrelu(fmaf(xv, w1v[u],     cgv[u]));
                float h1v= lrelu(fmaf(xv, w1v[u + 1], cgv[u + 1]));
                __half2 vh, vl;
                splitw(h0,  vh.x, vl.x);
                splitw(h1v, vh.y, vl.y);
                *(__half2*)(sAh + row * PA + k * 2) = vh;
                *(__half2*)(sAl + row * PA + k * 2) = vl;
            }
        }
    }
    CP_WAIT0();
    __syncthreads();                                   // B1: h1 + gW2

    float C[2][8][4];

    // ---- stage 2: h2 = h1 + lrelu(h1 @ gW2 + gb2) ----
    #pragma unroll
    for (int t = 0; t < 2; ++t)
        #pragma unroll
        for (int n = 0; n < 8; ++n)
            C[t][n][0] = C[t][n][1] = C[t][n][2] = C[t][n][3] = 0.f;
    gemm_2m<8, 4, PA, PA>(uAh + aOffA, uAl + aOffA, uW + wOffA, C);
    __syncthreads();                                   // B2a: gW2 dead
    cpa(uW + W_F1, d_wf1h, 10240, tid);
    cpa(uW + W_G3, d_wg3h, 8704, tid);
    CP_COMMIT();                                       // G1 under epilogue
    #pragma unroll
    for (int t = 0; t < 2; ++t) {
        int ra = r0 + 16 * t, rb = ra + 8;
        #pragma unroll
        for (int nt = 0; nt < 8; ++nt) {
            int col = nc0 + nt * 8 + c2;
            float b0 = __ldg(gb2 + col), b1 = __ldg(gb2 + col + 1);
            {
                __half2 hh = *(__half2*)(sAh + ra * PA + col * 2);
                __half2 ll = *(__half2*)(sAl + ra * PA + col * 2);
                float v0 = __half2float(hh.x) + __half2float(ll.x) + lrelu(C[t][nt][0] + b0);
                float v1 = __half2float(hh.y) + __half2float(ll.y) + lrelu(C[t][nt][1] + b1);
                __half2 vh, vl; splitw(v0, vh.x, vl.x); splitw(v1, vh.y, vl.y);
                *(__half2*)(sAh + ra * PA + col * 2) = vh;
                *(__half2*)(sAl + ra * PA + col * 2) = vl;
            }
            {
                __half2 hh = *(__half2*)(sAh + rb * PA + col * 2);
                __half2 ll = *(__half2*)(sAl + rb * PA + col * 2);
                float v0 = __half2float(hh.x) + __half2float(ll.x) + lrelu(C[t][nt][2] + b0);
                float v1 = __half2float(hh.y) + __half2float(ll.y) + lrelu(C[t][nt][3] + b1);
                __half2 vh, vl; splitw(v0, vh.x, vl.x); splitw(v1, vh.y, vl.y);
                *(__half2*)(sAh + rb * PA + col * 2) = vh;
                *(__half2*)(sAl + rb * PA + col * 2) = vl;
            }
        }
    }
    CP_WAIT0();
    __syncthreads();                                   // B2b: h2 + G3/F1

    // ---- stage 3: e = h2 @ gW3 + gb3 (N=32 -> 1 pair per nh) ----
    #pragma unroll
    for (int t = 0; t < 2; ++t)
        #pragma unroll
        for (int n = 0; n < 2; ++n)
            C[t][n][0] = C[t][n][1] = C[t][n][2] = C[t][n][3] = 0.f;
    gemm_2m<8, 1, PA, PA>(uAh + aOffA, uAl + aOffA, uW + W_G3 + wOffG3, C);
    #pragma unroll
    for (int t = 0; t < 2; ++t) {
        int ra = r0 + 16 * t, rb = ra + 8;
        #pragma unroll
        for (int nt = 0; nt < 2; ++nt) {
            int col = nh * 16 + nt * 8 + c2;
            float b0 = __ldg(gb3 + col), b1 = __ldg(gb3 + col + 1);
            *(float2*)&sE[ra * PE + col] = make_float2(C[t][nt][0] + b0, C[t][nt][1] + b1);
            *(float2*)&sE[rb * PE + col] = make_float2(C[t][nt][2] + b0, C[t][nt][3] + b1);
        }
    }
    __syncthreads();                                   // B3: sE done, h2/A free

    // ---- stage 4: aggregation -> ag split fp16 (PG) ----
    {
        float acc[16];
        #pragma unroll
        for (int d = 0; d < 16; ++d) acc[d] = 0.f;
        int i = rowH & 31;
        int bbase = rowH & ~31;
        #pragma unroll 4
        for (int j = 0; j < 32; ++j) {
            float w = sAdj[i * 33 + j];
            const float* er = &sE[(bbase + j) * PE + hf * 16];
            #pragma unroll
            for (int qq = 0; qq < 4; ++qq) {
                float4 ev = *(const float4*)&er[qq * 4];
                acc[qq * 4 + 0] = fmaf(w, ev.x, acc[qq * 4 + 0]);
                acc[qq * 4 + 1] = fmaf(w, ev.y, acc[qq * 4 + 1]);
                acc[qq * 4 + 2] = fmaf(w, ev.z, acc[qq * 4 + 2]);
                acc[qq * 4 + 3] = fmaf(w, ev.w, acc[qq * 4 + 3]);
            }
        }
        #pragma unroll
        for (int d = 0; d < 16; d += 2) {
            int k = hf * 16 + d;
            __half2 vh, vl;
            splitw(acc[d],     vh.x, vl.x);
            splitw(acc[d + 1], vh.y, vl.y);
            *(__half2*)(sAh + rowH * PG + k * 2) = vh;
            *(__half2*)(sAl + rowH * PG + k * 2) = vl;
        }
    }
    __syncthreads();                                   // B4: ag visible

    // ---- stage 5: p1 = lrelu(ag @ fW1 + c_f) (K=32) ----
    #pragma unroll
    for (int t = 0; t < 2; ++t)
        #pragma unroll
        for (int n = 0; n < 8; ++n)
            C[t][n][0] = C[t][n][1] = C[t][n][2] = C[t][n][3] = 0.f;
    gemm_2m<2, 4, PG, PF1>(uAh + aOffG, uAl + aOffG, uW + W_F1 + wOffF1, C);
    __syncthreads();                                   // B5a: ag/F1/E dead
    cpa(uW, d_wf2h, 34816, tid);
    CP_COMMIT();                                       // G2 under epilogue
    #pragma unroll
    for (int t = 0; t < 2; ++t) {
        int ra = r0 + 16 * t, rb = ra + 8;
        const float* cfa = d_cf + (ra & 31) * 128;
        const float* cfb = d_cf + (rb & 31) * 128;
        #pragma unroll
        for (int nt = 0; nt < 8; ++nt) {
            int col = nc0 + nt * 8 + c2;
            float v0 = lrelu(C[t][nt][0] + __ldg(cfa + col));
            float v1 = lrelu(C[t][nt][1] + __ldg(cfa + col + 1));
            float v2 = lrelu(C[t][nt][2] + __ldg(cfb + col));
            float v3 = lrelu(C[t][nt][3] + __ldg(cfb + col + 1));
            __half2 vh, vl;
            splitw(v0, vh.x, vl.x); splitw(v1, vh.y, vl.y);
            *(__half2*)(sAh + ra * PA + col * 2) = vh;
            *(__half2*)(sAl + ra * PA + col * 2) = vl;
            splitw(v2, vh.x, vl.x); splitw(v3, vh.y, vl.y);
            *(__half2*)(sAh + rb * PA + col * 2) = vh;
            *(__half2*)(sAl + rb * PA + col * 2) = vl;
        }
    }
    CP_WAIT0();
    __syncthreads();                                   // B5b: p1 + fW2

    // ---- stage 6: p1 @ fW2 ----
    #pragma unroll
    for (int t = 0; t < 2; ++t)
        #pragma unroll
        for (int n = 0; n < 8; ++n)
            C[t][n][0] = C[t][n][1] = C[t][n][2] = C[t][n][3] = 0.f;
    gemm_2m<8, 4, PA, PA>(uAh + aOffA, uAl + aOffA, uW + wOffA, C);
    __syncthreads();                                   // B6a: fW2 dead
    // F3 repack fp32 [a=128][i=32] -> pitch 36 floats
    for (int idx = tid; idx < 1024; idx += 512) {
        int a = idx >> 3, c = idx & 7;
        CP16(uW + a * (PF3 * 4) + c * 16, fW3 + a * 32 + c * 4);
    }
    CP_COMMIT();

    // ---- stage 7a: p2 into C (overlaps F3 flight) ----
    #pragma unroll
    for (int t = 0; t < 2; ++t) {
        int ra = r0 + 16 * t, rb = ra + 8;
        #pragma unroll
        for (int nt = 0; nt < 8; ++nt) {
            int col = nc0 + nt * 8 + c2;
            float b0 = __ldg(fb2 + col), b1 = __ldg(fb2 + col + 1);
            __half2 hh = *(__half2*)(sAh + ra * PA + col * 2);
            __half2 ll = *(__half2*)(sAl + ra * PA + col * 2);
            C[t][nt][0] = __half2float(hh.x) + __half2float(ll.x) + lrelu(C[t][nt][0] + b0);
            C[t][nt][1] = __half2float(hh.y) + __half2float(ll.y) + lrelu(C[t][nt][1] + b1);
            hh = *(__half2*)(sAh + rb * PA + col * 2);
            ll = *(__half2*)(sAl + rb * PA + col * 2);
            C[t][nt][2] = __half2float(hh.x) + __half2float(ll.x) + lrelu(C[t][nt][2] + b0);
            C[t][nt][3] = __half2float(hh.y) + __half2float(ll.y) + lrelu(C[t][nt][3] + b1);
        }
    }
    CP_WAIT0();
    __syncthreads();                                   // B6b: F3 visible

    // ---- stage 7b: dot with fW3, reduce, partials ----
    {
        const float* sW3 = (const float*)(sm + OFF_W);
        float acc[2][2] = {{0.f, 0.f}, {0.f, 0.f}};
        #pragma unroll
        for (int t = 0; t < 2; ++t) {
            int ra = r0 + 16 * t, rb = ra + 8;
            int ia = ra & 31, ib = rb & 31;
            #pragma unroll
            for (int nt = 0; nt < 8; ++nt) {
                int col = nc0 + nt * 8 + c2;
                acc[t][0] = fmaf(C[t][nt][0], sW3[col * PF3 + ia], acc[t][0]);
                acc[t][0] = fmaf(C[t][nt][1], sW3[(col + 1) * PF3 + ia], acc[t][0]);
                acc[t][1] = fmaf(C[t][nt][2], sW3[col * PF3 + ib], acc[t][1]);
                acc[t][1] = fmaf(C[t][nt][3], sW3[(col + 1) * PF3 + ib], acc[t][1]);
            }
        }
        #pragma unroll
        for (int t = 0; t < 2; ++t) {
            acc[t][0] += __shfl_xor_sync(0xffffffffu, acc[t][0], 1);
            acc[t][0] += __shfl_xor_sync(0xffffffffu, acc[t][0], 2);
            acc[t][1] += __shfl_xor_sync(0xffffffffu, acc[t][1], 1);
            acc[t][1] += __shfl_xor_sync(0xffffffffu, acc[t][1], 2);
        }
        __syncthreads();                               // sPx: sX -> partials
        if ((lane & 3) == 0) {
            #pragma unroll
            for (int t = 0; t < 2; ++t) {
                sPx[nh * 256 + r0 + 16 * t]     = acc[t][0];
                sPx[nh * 256 + r0 + 16 * t + 8] = acc[t][1];
            }
        }
    }
    __syncthreads();                                   // B7
    if (tid < 256)
        out[blockIdx.x * 256 + tid] = sPx[tid] + sPx[256 + tid] + __ldg(fb3 + (tid & 31));
}

// ---------------------------------------------------------------------------
extern "C" void kernel_launch(void* const* d_in, const int* in_sizes, int n_in,
                              void* d_out, int out_size) {
    const float* X   = (const float*)d_in[0];
    const float* W   = (const float*)d_in[1];
    const float* emb = (const float*)d_in[2];
    const float* gW1 = (const float*)d_in[3];
    const float* gb1 = (const float*)d_in[4];
    const float* gW2 = (const float*)d_in[5];
    const float* gb2 = (const float*)d_in[6];
    const float* gW3 = (const float*)d_in[7];
    const float* gb3 = (const float*)d_in[8];
    const float* fW1 = (const float*)d_in[9];
    const float* fb1 = (const float*)d_in[10];
    const float* fW2 = (const float*)d_in[11];
    const float* fb2 = (const float*)d_in[12];
    const float* fW3 = (const float*)d_in[13];
    const float* fb3 = (const float*)d_in[14];
    float* out = (float*)d_out;

    int B = in_sizes[0] / 32;

    cudaFuncSetAttribute(fused_gnn_kernel,
                         cudaFuncAttributeMaxDynamicSharedMemorySize, SMEM_BYTES);

    setup_kernel<<<160, 256>>>(W, emb, gW1, gb1, gW2, gW3, fW1, fb1, fW2);
    fused_gnn_kernel<<<B / 8, 512, SMEM_BYTES>>>(X, gW1, gb2, gb3, fb2, fW3, fb3, out);
}

// round 11
// speedup vs baseline: 4.6936x; 1.3630x over previous
#include <cuda_runtime.h>
#include <cuda_fp16.h>
#include <cstdint>

// ---------------------------------------------------------------------------
// ContractiveInvertibleGNN — mma.sync plain fp16, 256-row CTA, 32x64 warp
// tiles. A and B both single fp16 (quant error 2^-12 each side, predicted
// rel_err ~3.6e-4 vs 1e-3 gate; measured B-only was 2.57e-4).
// SMEM W region time-multiplexed: gW2 -> {E | fW1 | gW3} -> fW2 -> fW3.
// ---------------------------------------------------------------------------

#define PA  272     // activation row pitch (128 fp16 + 16B pad)
#define PG  80      // ag row pitch (32 fp16 + pad)
#define PF1 80      // fW1 row pitch — 16B multiple (ldmatrix)
#define PE  32      // e pitch in floats (128B)
#define PF3 36      // fW3 pitch in floats (144B)

#define OFF_AH   0          // 69632 = 256*272
#define OFF_W    69632      // 51712: gW2 -> {E | F1 | G3} -> fW2 -> F3
#define OFF_ADJ  121344     // 4224 (33*32*4)
#define OFF_PART 125568     // 2048 (sX early, partials late)
#define SMEM_BYTES 127616

#define W_E   0             // 32768 (256 rows * 128B)
#define W_F1  32768         // 10240
#define W_G3  43008         // 8704

// ---- preformatted fp16 weights ----
__device__ __align__(256) char d_wg2h[34816];  // gW2^T [n128][k128] p272
__device__ __align__(256) char d_wg3h[8704];   // gW3^T [n32][k128]  p272
__device__ __align__(256) char d_wf1h[10240];  // fW1^T [n128][k32]  p80
__device__ __align__(256) char d_wf2h[34816];  // fW2^T [n128][k128] p272
__device__ float d_cg[4096], d_cf[4096], d_wadjT[1024];

__device__ __forceinline__ float lrelu(float x) { return x > 0.f ? x : 0.01f * x; }
__device__ __forceinline__ uint32_t smem_u32(const void* p) {
    uint32_t a;
    asm("{ .reg .u64 t; cvta.to.shared.u64 t, %1; cvt.u32.u64 %0, t; }" : "=r"(a) : "l"(p));
    return a;
}

#define LDSM_X4(r0, r1, r2, r3, addr)                                        \
    asm volatile("ldmatrix.sync.aligned.m8n8.x4.shared.b16 {%0,%1,%2,%3}, [%4];" \
                 : "=r"(r0), "=r"(r1), "=r"(r2), "=r"(r3) : "r"(addr))
#define CP16(d, s) \
    asm volatile("cp.async.ca.shared.global [%0], [%1], 16;" \
                 :: "r"(d), "l"((unsigned long long)__cvta_generic_to_global(s)) : "memory")
#define CP_COMMIT() asm volatile("cp.async.commit_group;" ::: "memory")
#define CP_WAIT0()  asm volatile("cp.async.wait_group 0;" ::: "memory")

__device__ __forceinline__ void mma16816(float* c, const uint32_t* a,
                                         uint32_t b0, uint32_t b1) {
    asm volatile("mma.sync.aligned.m16n8k16.row.col.f32.f16.f16.f32 "
                 "{%0,%1,%2,%3}, {%4,%5,%6,%7}, {%8,%9}, {%0,%1,%2,%3};"
                 : "+f"(c[0]), "+f"(c[1]), "+f"(c[2]), "+f"(c[3])
                 : "r"(a[0]), "r"(a[1]), "r"(a[2]), "r"(a[3]), "r"(b0), "r"(b1));
}

// 2-m-tile fp16 GEMM: C += A @ B. C[2][8][4]; only the first 2*NPAIR
// n-tiles per m-tile are touched.
template <int KS, int NPAIR, int AP, int WP>
__device__ __forceinline__ void gemm_2m(uint32_t aH, uint32_t wH,
                                        float C[2][8][4]) {
    #pragma unroll
    for (int k = 0; k < KS; ++k) {
        uint32_t ah[2][4];
        LDSM_X4(ah[0][0], ah[0][1], ah[0][2], ah[0][3], aH + k * 32);
        LDSM_X4(ah[1][0], ah[1][1], ah[1][2], ah[1][3], aH + 16 * AP + k * 32);
        #pragma unroll
        for (int p = 0; p < NPAIR; ++p) {
            uint32_t bh0, bh1, bh2, bh3;
            LDSM_X4(bh0, bh1, bh2, bh3, wH + p * 16 * WP + k * 32);
            #pragma unroll
            for (int t = 0; t < 2; ++t) {
                mma16816(C[t][2 * p],     ah[t], bh0, bh2);
                mma16816(C[t][2 * p + 1], ah[t], bh1, bh3);
            }
        }
    }
}

// ---------------------------------------------------------------------------
__global__ void setup_kernel(const float* __restrict__ W, const float* __restrict__ emb,
                             const float* __restrict__ gW1, const float* __restrict__ gb1,
                             const float* __restrict__ gW2, const float* __restrict__ gW3,
                             const float* __restrict__ fW1, const float* __restrict__ fb1,
                             const float* __restrict__ fW2) {
    int t = blockIdx.x * blockDim.x + threadIdx.x;
    if (t < 4096) {
        int i = t >> 7, a = t & 127;
        float sg = gb1[a], sf = fb1[a];
        #pragma unroll
        for (int e = 0; e < 32; ++e) {
            float em = emb[i * 32 + e];
            sg = fmaf(em, gW1[(32 + e) * 128 + a], sg);
            sf = fmaf(em, fW1[(32 + e) * 128 + a], sf);
        }
        d_cg[t] = sg;
        d_cf[t] = sf;
    }
    if (t < 1024) {
        int i = t >> 5, j = t & 31;
        d_wadjT[t] = (i == j) ? 0.f : W[j * 32 + i];
    }
    if (t < 16384) {                       // gW2^T
        int n = t >> 7, k = t & 127;
        *(__half*)(d_wg2h + n * PA + k * 2) = __float2half_rn(gW2[k * 128 + n]);
    } else if (t < 20480) {                // gW3^T
        int u = t - 16384, n = u >> 7, k = u & 127;
        *(__half*)(d_wg3h + n * PA + k * 2) = __float2half_rn(gW3[k * 32 + n]);
    } else if (t < 24576) {                // fW1[:32]^T
        int u = t - 20480, n = u >> 5, k = u & 31;
        *(__half*)(d_wf1h + n * PF1 + k * 2) = __float2half_rn(fW1[k * 128 + n]);
    } else if (t < 40960) {                // fW2^T
        int u = t - 24576, n = u >> 7, k = u & 127;
        *(__half*)(d_wf2h + n * PA + k * 2) = __float2half_rn(fW2[k * 128 + n]);
    }
}

__device__ __forceinline__ void cpa(uint32_t dst, const void* src, int size, int tid) {
    const char* s = (const char*)src;
    for (int o = tid * 16; o < size; o += 512 * 16) CP16(dst + o, s + o);
}

// ---------------------------------------------------------------------------
__global__ __launch_bounds__(512, 1)
void fused_gnn_kernel(const float* __restrict__ X,
                      const float* __restrict__ gW1,
                      const float* __restrict__ gb2, const float* __restrict__ gb3,
                      const float* __restrict__ fb2,
                      const float* __restrict__ fW3, const float* __restrict__ fb3,
                      float* __restrict__ out) {
    extern __shared__ char sm[];
    const uint32_t smb = smem_u32(sm);
    const int tid = threadIdx.x;
    const int wid = tid >> 5, lane = tid & 31;
    const int mw = wid & 7, nh = wid >> 3;
    const int m0 = mw * 32;
    const int rowH = tid >> 1, hf = tid & 1;

    char*  sAh  = sm + OFF_AH;
    float* sE   = (float*)(sm + OFF_W + W_E);
    float* sAdj = (float*)(sm + OFF_ADJ);
    float* sPx  = (float*)(sm + OFF_PART);   // sX early, partials late
    const uint32_t uAh = smb + OFF_AH;
    const uint32_t uW = smb + OFF_W;

    const int r0 = m0 + (lane >> 2);
    const int c2 = 2 * (lane & 3);
    const int nc0 = nh * 64;

    const uint32_t aOffA = (uint32_t)((m0 + (lane & 15)) * PA + (lane >> 4) * 16);
    const uint32_t aOffG = (uint32_t)((m0 + (lane & 15)) * PG + (lane >> 4) * 16);
    const uint32_t wrow  = (uint32_t)((lane & 7) + 8 * ((lane >> 3) & 1));
    const uint32_t wOffA  = (uint32_t)((nc0 + wrow) * PA + (lane >> 4) * 16);
    const uint32_t wOffG3 = (uint32_t)((nh * 16 + wrow) * PA + (lane >> 4) * 16);
    const uint32_t wOffF1 = (uint32_t)((nc0 + wrow) * PF1 + (lane >> 4) * 16);

    // ---- prologue: gW2 prefetch (G0) + X/adj staging ----
    cpa(uW, d_wg2h, 34816, tid);
    CP_COMMIT();
    if (tid < 256) sPx[tid] = X[blockIdx.x * 256 + tid];
    for (int idx = tid; idx < 1024; idx += 512)
        sAdj[(idx >> 5) * 33 + (idx & 31)] = d_wadjT[idx];
    __syncthreads();                                   // B0: sX visible

    // ---- stage 1: h1. thread = (i, k-chunk) x 8 batches ----
    {
        int i = tid & 31, kc = tid >> 5;               // kc 0..15
        float w1v[8], cgv[8];
        #pragma unroll
        for (int u = 0; u < 8; ++u) {
            int k = kc * 8 + u;
            w1v[u] = __ldg(gW1 + i * 128 + k);
            cgv[u] = __ldg(d_cg + i * 128 + k);
        }
        #pragma unroll
        for (int b = 0; b < 8; ++b) {
            int row = b * 32 + i;
            float xv = sPx[row];
            #pragma unroll
            for (int u = 0; u < 8; u += 2) {
                int k = kc * 8 + u;
                float h0 = lrelu(fmaf(xv, w1v[u],     cgv[u]));
                float h1v= lrelu(fmaf(xv, w1v[u + 1], cgv[u + 1]));
                *(__half2*)(sAh + row * PA + k * 2) =
                    __half2(__float2half_rn(h0), __float2half_rn(h1v));
            }
        }
    }
    CP_WAIT0();
    __syncthreads();                                   // B1: h1 + gW2

    float C[2][8][4];

    // ---- stage 2: h2 = h1 + lrelu(h1 @ gW2 + gb2) ----
    #pragma unroll
    for (int t = 0; t < 2; ++t)
        #pragma unroll
        for (int n = 0; n < 8; ++n)
            C[t][n][0] = C[t][n][1] = C[t][n][2] = C[t][n][3] = 0.f;
    gemm_2m<8, 4, PA, PA>(uAh + aOffA, uW + wOffA, C);
    __syncthreads();                                   // B2a: gW2 dead
    cpa(uW + W_F1, d_wf1h, 10240, tid);
    cpa(uW + W_G3, d_wg3h, 8704, tid);
    CP_COMMIT();                                       // G1 under epilogue
    #pragma unroll
    for (int t = 0; t < 2; ++t) {
        int ra = r0 + 16 * t, rb = ra + 8;
        #pragma unroll
        for (int nt = 0; nt < 8; ++nt) {
            int col = nc0 + nt * 8 + c2;
            float b0 = __ldg(gb2 + col), b1 = __ldg(gb2 + col + 1);
            {
                __half2 hh = *(__half2*)(sAh + ra * PA + col * 2);
                float v0 = __half2float(hh.x) + lrelu(C[t][nt][0] + b0);
                float v1 = __half2float(hh.y) + lrelu(C[t][nt][1] + b1);
                *(__half2*)(sAh + ra * PA + col * 2) =
                    __half2(__float2half_rn(v0), __float2half_rn(v1));
            }
            {
                __half2 hh = *(__half2*)(sAh + rb * PA + col * 2);
                float v0 = __half2float(hh.x) + lrelu(C[t][nt][2] + b0);
                float v1 = __half2float(hh.y) + lrelu(C[t][nt][3] + b1);
                *(__half2*)(sAh + rb * PA + col * 2) =
                    __half2(__float2half_rn(v0), __float2half_rn(v1));
            }
        }
    }
    CP_WAIT0();
    __syncthreads();                                   // B2b: h2 + G3/F1

    // ---- stage 3: e = h2 @ gW3 + gb3 (N=32 -> 1 pair per nh) ----
    #pragma unroll
    for (int t = 0; t < 2; ++t)
        #pragma unroll
        for (int n = 0; n < 2; ++n)
            C[t][n][0] = C[t][n][1] = C[t][n][2] = C[t][n][3] = 0.f;
    gemm_2m<8, 1, PA, PA>(uAh + aOffA, uW + W_G3 + wOffG3, C);
    #pragma unroll
    for (int t = 0; t < 2; ++t) {
        int ra = r0 + 16 * t, rb = ra + 8;
        #pragma unroll
        for (int nt = 0; nt < 2; ++nt) {
            int col = nh * 16 + nt * 8 + c2;
            float b0 = __ldg(gb3 + col), b1 = __ldg(gb3 + col + 1);
            *(float2*)&sE[ra * PE + col] = make_float2(C[t][nt][0] + b0, C[t][nt][1] + b1);
            *(float2*)&sE[rb * PE + col] = make_float2(C[t][nt][2] + b0, C[t][nt][3] + b1);
        }
    }
    __syncthreads();                                   // B3: sE done, h2/A free

    // ---- stage 4: aggregation -> ag fp16 (PG) ----
    {
        float acc[16];
        #pragma unroll
        for (int d = 0; d < 16; ++d) acc[d] = 0.f;
        int i = rowH & 31;
        int bbase = rowH & ~31;
        #pragma unroll 4
        for (int j = 0; j < 32; ++j) {
            float w = sAdj[i * 33 + j];
            const float* er = &sE[(bbase + j) * PE + hf * 16];
            #pragma unroll
            for (int qq = 0; qq < 4; ++qq) {
                float4 ev = *(const float4*)&er[qq * 4];
                acc[qq * 4 + 0] = fmaf(w, ev.x, acc[qq * 4 + 0]);
                acc[qq * 4 + 1] = fmaf(w, ev.y, acc[qq * 4 + 1]);
                acc[qq * 4 + 2] = fmaf(w, ev.z, acc[qq * 4 + 2]);
                acc[qq * 4 + 3] = fmaf(w, ev.w, acc[qq * 4 + 3]);
            }
        }
        #pragma unroll
        for (int d = 0; d < 16; d += 2) {
            int k = hf * 16 + d;
            *(__half2*)(sAh + rowH * PG + k * 2) =
                __half2(__float2half_rn(acc[d]), __float2half_rn(acc[d + 1]));
        }
    }
    __syncthreads();                                   // B4: ag visible

    // ---- stage 5: p1 = lrelu(ag @ fW1 + c_f) (K=32) ----
    #pragma unroll
    for (int t = 0; t < 2; ++t)
        #pragma unroll
        for (int n = 0; n < 8; ++n)
            C[t][n][0] = C[t][n][1] = C[t][n][2] = C[t][n][3] = 0.f;
    gemm_2m<2, 4, PG, PF1>(uAh + aOffG, uW + W_F1 + wOffF1, C);
    __syncthreads();                                   // B5a: ag/F1/E dead
    cpa(uW, d_wf2h, 34816, tid);
    CP_COMMIT();                                       // G2 under epilogue
    #pragma unroll
    for (int t = 0; t < 2; ++t) {
        int ra = r0 + 16 * t, rb = ra + 8;
        const float* cfa = d_cf + (ra & 31) * 128;
        const float* cfb = d_cf + (rb & 31) * 128;
        #pragma unroll
        for (int nt = 0; nt < 8; ++nt) {
            int col = nc0 + nt * 8 + c2;
            float v0 = lrelu(C[t][nt][0] + __ldg(cfa + col));
            float v1 = lrelu(C[t][nt][1] + __ldg(cfa + col + 1));
            float v2 = lrelu(C[t][nt][2] + __ldg(cfb + col));
            float v3 = lrelu(C[t][nt][3] + __ldg(cfb + col + 1));
            *(__half2*)(sAh + ra * PA + col * 2) =
                __half2(__float2half_rn(v0), __float2half_rn(v1));
            *(__half2*)(sAh + rb * PA + col * 2) =
                __half2(__float2half_rn(v2), __float2half_rn(v3));
        }
    }
    CP_WAIT0();
    __syncthreads();                                   // B5b: p1 + fW2

    // ---- stage 6: p1 @ fW2 ----
    #pragma unroll
    for (int t = 0; t < 2; ++t)
        #pragma unroll
        for (int n = 0; n < 8; ++n)
            C[t][n][0] = C[t][n][1] = C[t][n][2] = C[t][n][3] = 0.f;
    gemm_2m<8, 4, PA, PA>(uAh + aOffA, uW + wOffA, C);
    __syncthreads();                                   // B6a: fW2 dead
    // F3 repack fp32 [a=128][i=32] -> pitch 36 floats
    for (int idx = tid; idx < 1024; idx += 512) {
        int a = idx >> 3, c = idx & 7;
        CP16(uW + a * (PF3 * 4) + c * 16, fW3 + a * 32 + c * 4);
    }
    CP_COMMIT();

    // ---- stage 7a: p2 into C (overlaps F3 flight) ----
    #pragma unroll
    for (int t = 0; t < 2; ++t) {
        int ra = r0 + 16 * t, rb = ra + 8;
        #pragma unroll
        for (int nt = 0; nt < 8; ++nt) {
            int col = nc0 + nt * 8 + c2;
            float b0 = __ldg(fb2 + col), b1 = __ldg(fb2 + col + 1);
            __half2 hh = *(__half2*)(sAh + ra * PA + col * 2);
            C[t][nt][0] = __half2float(hh.x) + lrelu(C[t][nt][0] + b0);
            C[t][nt][1] = __half2float(hh.y) + lrelu(C[t][nt][1] + b1);
            hh = *(__half2*)(sAh + rb * PA + col * 2);
            C[t][nt][2] = __half2float(hh.x) + lrelu(C[t][nt][2] + b0);
            C[t][nt][3] = __half2float(hh.y) + lrelu(C[t][nt][3] + b1);
        }
    }
    CP_WAIT0();
    __syncthreads();                                   // B6b: F3 visible

    // ---- stage 7b: dot with fW3, reduce, partials ----
    {
        const float* sW3 = (const float*)(sm + OFF_W);
        float acc[2][2] = {{0.f, 0.f}, {0.f, 0.f}};
        #pragma unroll
        for (int t = 0; t < 2; ++t) {
            int ra = r0 + 16 * t, rb = ra + 8;
            int ia = ra & 31, ib = rb & 31;
            #pragma unroll
            for (int nt = 0; nt < 8; ++nt) {
                int col = nc0 + nt * 8 + c2;
                acc[t][0] = fmaf(C[t][nt][0], sW3[col * PF3 + ia], acc[t][0]);
                acc[t][0] = fmaf(C[t][nt][1], sW3[(col + 1) * PF3 + ia], acc[t][0]);
                acc[t][1] = fmaf(C[t][nt][2], sW3[col * PF3 + ib], acc[t][1]);
                acc[t][1] = fmaf(C[t][nt][3], sW3[(col + 1) * PF3 + ib], acc[t][1]);
            }
        }
        #pragma unroll
        for (int t = 0; t < 2; ++t) {
            acc[t][0] += __shfl_xor_sync(0xffffffffu, acc[t][0], 1);
            acc[t][0] += __shfl_xor_sync(0xffffffffu, acc[t][0], 2);
            acc[t][1] += __shfl_xor_sync(0xffffffffu, acc[t][1], 1);
            acc[t][1] += __shfl_xor_sync(0xffffffffu, acc[t][1], 2);
        }
        __syncthreads();                               // sPx: sX -> partials
        if ((lane & 3) == 0) {
            #pragma unroll
            for (int t = 0; t < 2; ++t) {
                sPx[nh * 256 + r0 + 16 * t]     = acc[t][0];
                sPx[nh * 256 + r0 + 16 * t + 8] = acc[t][1];
            }
        }
    }
    __syncthreads();                                   // B7
    if (tid < 256)
        out[blockIdx.x * 256 + tid] = sPx[tid] + sPx[256 + tid] + __ldg(fb3 + (tid & 31));
}

// ---------------------------------------------------------------------------
extern "C" void kernel_launch(void* const* d_in, const int* in_sizes, int n_in,
                              void* d_out, int out_size) {
    const float* X   = (const float*)d_in[0];
    const float* W   = (const float*)d_in[1];
    const float* emb = (const float*)d_in[2];
    const float* gW1 = (const float*)d_in[3];
    const float* gb1 = (const float*)d_in[4];
    const float* gW2 = (const float*)d_in[5];
    const float* gb2 = (const float*)d_in[6];
    const float* gW3 = (const float*)d_in[7];
    const float* gb3 = (const float*)d_in[8];
    const float* fW1 = (const float*)d_in[9];
    const float* fb1 = (const float*)d_in[10];
    const float* fW2 = (const float*)d_in[11];
    const float* fb2 = (const float*)d_in[12];
    const float* fW3 = (const float*)d_in[13];
    const float* fb3 = (const float*)d_in[14];
    float* out = (float*)d_out;

    int B = in_sizes[0] / 32;

    cudaFuncSetAttribute(fused_gnn_kernel,
                         cudaFuncAttributeMaxDynamicSharedMemorySize, SMEM_BYTES);

    setup_kernel<<<160, 256>>>(W, emb, gW1, gb1, gW2, gW3, fW1, fb1, fW2);
    fused_gnn_kernel<<<B / 8, 512, SMEM_BYTES>>>(X, gW1, gb2, gb3, fb2, fW3, fb3, out);
}